// round 9
// baseline (speedup 1.0000x reference)
#include <cuda_runtime.h>
#include <math.h>

// Problem constants (fixed by the reference)
#define MAXN 100000
#define MAXE 1600000

// Scratch (device globals: allocation-free per harness rules).
// __align__(16) is load-bearing: float4 loads + red.v4 need 16B alignment.
__device__ __align__(16) float g_h[MAXN * 128];   // h = x @ W^T            (51.2 MB)
__device__ __align__(16) float g_ex[MAXE * 4];    // exp(leaky(e)) per edge (25.6 MB)
__device__ __align__(16) float g_asrc[MAXN * 4];  // a_src per node/head
__device__ __align__(16) float g_adst[MAXN * 4];  // a_dst per node/head
__device__ __align__(16) float g_s[MAXN * 4];     // softmax denominators

__device__ __forceinline__ void red_add_v4(float* addr, float a, float b, float c, float d) {
    asm volatile("red.global.add.v4.f32 [%0], {%1, %2, %3, %4};"
                 :: "l"(addr), "f"(a), "f"(b), "f"(c), "f"(d) : "memory");
}

// ---------------------------------------------------------------------------
// 0) zero out accumulator + denominators
// ---------------------------------------------------------------------------
__global__ void zero_kernel(float* __restrict__ out, int n) {
    int t = blockIdx.x * blockDim.x + threadIdx.x;
    int stride = gridDim.x * blockDim.x;
    float4 z = make_float4(0.f, 0.f, 0.f, 0.f);
    float4* o4 = (float4*)out;
    int n4 = n * 32;                      // n*128/4
    for (int i = t; i < n4; i += stride) o4[i] = z;
    float4* s4 = (float4*)g_s;            // n*4/4 = n float4s
    for (int i = t; i < n; i += stride) s4[i] = z;
}

// ---------------------------------------------------------------------------
// 1) h = x @ W^T  (FP32, W staged transposed in smem, 64-row tiles)
//    thread computes 4 rows x 8 cols
// ---------------------------------------------------------------------------
#define GEMM_SMEM ((64 * 132 + 128 * 132) * 4)   // 101376 bytes

__global__ void gemm_kernel(const float* __restrict__ x,
                            const float* __restrict__ W, int n) {
    extern __shared__ float sm[];
    float* xs = sm;               // [64][132]
    float* ws = sm + 64 * 132;    // [128][132]  ws[k][col] = W[col][k]
    int tid = threadIdx.x;
    int row0 = blockIdx.x * 64;

    for (int idx = tid; idx < 128 * 128; idx += 256) {
        int col = idx & 127, k = idx >> 7;
        ws[k * 132 + col] = W[col * 128 + k];
    }
    for (int idx = tid; idx < 64 * 128; idx += 256) {
        int r = idx >> 7, k = idx & 127;
        int gr = row0 + r;
        xs[r * 132 + k] = (gr < n) ? x[gr * 128 + k] : 0.0f;
    }
    __syncthreads();

    const int tx = tid & 15;      // col group: cols tx*8 .. tx*8+7
    const int ty = tid >> 4;      // row group: rows ty*4 .. ty*4+3
    float acc[4][8];
#pragma unroll
    for (int i = 0; i < 4; i++)
#pragma unroll
        for (int j = 0; j < 8; j++) acc[i][j] = 0.0f;

#pragma unroll 8
    for (int k = 0; k < 128; k++) {
        float4 w0 = *(const float4*)(ws + k * 132 + tx * 8);
        float4 w1 = *(const float4*)(ws + k * 132 + tx * 8 + 4);
#pragma unroll
        for (int i = 0; i < 4; i++) {
            float xv = xs[(ty * 4 + i) * 132 + k];
            acc[i][0] += xv * w0.x; acc[i][1] += xv * w0.y;
            acc[i][2] += xv * w0.z; acc[i][3] += xv * w0.w;
            acc[i][4] += xv * w1.x; acc[i][5] += xv * w1.y;
            acc[i][6] += xv * w1.z; acc[i][7] += xv * w1.w;
        }
    }

#pragma unroll
    for (int i = 0; i < 4; i++) {
        int row = row0 + ty * 4 + i;
        if (row < n) {
            float4 o0 = make_float4(acc[i][0], acc[i][1], acc[i][2], acc[i][3]);
            float4 o1 = make_float4(acc[i][4], acc[i][5], acc[i][6], acc[i][7]);
            *(float4*)(g_h + row * 128 + tx * 8)     = o0;
            *(float4*)(g_h + row * 128 + tx * 8 + 4) = o1;
        }
    }
}

// ---------------------------------------------------------------------------
// 2) a_src[n,h] = <h[n,h,:], att_src[h,:]>   (warp per node)
// ---------------------------------------------------------------------------
__global__ void attn_kernel(const float* __restrict__ att_src,
                            const float* __restrict__ att_dst, int n) {
    int lane = threadIdx.x & 31;
    int wid = (blockIdx.x * blockDim.x + threadIdx.x) >> 5;
    int nw = (gridDim.x * blockDim.x) >> 5;
    float4 as4 = *(const float4*)&att_src[lane * 4];
    float4 ad4 = *(const float4*)&att_dst[lane * 4];
    int head = lane >> 3;
    for (int nid = wid; nid < n; nid += nw) {
        float4 hv = *(const float4*)&g_h[nid * 128 + lane * 4];
        float ps = hv.x * as4.x + hv.y * as4.y + hv.z * as4.z + hv.w * as4.w;
        float pd = hv.x * ad4.x + hv.y * ad4.y + hv.z * ad4.z + hv.w * ad4.w;
#pragma unroll
        for (int o = 4; o >= 1; o >>= 1) {
            ps += __shfl_xor_sync(0xFFFFFFFFu, ps, o);
            pd += __shfl_xor_sync(0xFFFFFFFFu, pd, o);
        }
        if ((lane & 7) == 0) {
            g_asrc[nid * 4 + head] = ps;
            g_adst[nid * 4 + head] = pd;
        }
    }
}

// ---------------------------------------------------------------------------
// 3) per edge: ex = exp(leaky_relu(a_src[src]+a_dst[dst])); s[dst] += ex
//    (segment-max skipped: softmax is shift-invariant, logits are O(5))
//    NOTE: edge_index is int32 on device (JAX x64 disabled downcasts int64).
// ---------------------------------------------------------------------------
__global__ void edge_pre_kernel(const int* __restrict__ src,
                                const int* __restrict__ dst, int e) {
    int t = blockIdx.x * blockDim.x + threadIdx.x;
    int stride = gridDim.x * blockDim.x;
    for (int i = t; i < e; i += stride) {
        int s = src[i];
        int d = dst[i];
        float4 a = *(const float4*)&g_asrc[s * 4];
        float4 b = *(const float4*)&g_adst[d * 4];
        float t0 = a.x + b.x, t1 = a.y + b.y, t2 = a.z + b.z, t3 = a.w + b.w;
        float4 v;
        v.x = expf(t0 > 0.f ? t0 : 0.2f * t0);
        v.y = expf(t1 > 0.f ? t1 : 0.2f * t1);
        v.z = expf(t2 > 0.f ? t2 : 0.2f * t2);
        v.w = expf(t3 > 0.f ? t3 : 0.2f * t3);
        *(float4*)&g_ex[i * 4] = v;
        red_add_v4(&g_s[d * 4], v.x, v.y, v.z, v.w);
    }
}

// ---------------------------------------------------------------------------
// 4) per edge (one warp): out[dst] += h[src] * alpha   (vectorized red)
// ---------------------------------------------------------------------------
__global__ void edge_agg_kernel(const int* __restrict__ src,
                                const int* __restrict__ dst,
                                float* __restrict__ out, int e) {
    int lane = threadIdx.x & 31;
    int wid = (blockIdx.x * blockDim.x + threadIdx.x) >> 5;
    int nw = (gridDim.x * blockDim.x) >> 5;
    int head = lane >> 3;
    for (int i = wid; i < e; i += nw) {
        int s = src[i];
        int d = dst[i];
        float exv = g_ex[i * 4 + head];
        float sv = g_s[d * 4 + head];
        float alpha = exv / (sv + 1e-16f);
        float4 hv = *(const float4*)&g_h[s * 128 + lane * 4];
        red_add_v4(&out[d * 128 + lane * 4],
                   hv.x * alpha, hv.y * alpha, hv.z * alpha, hv.w * alpha);
    }
}

// ---------------------------------------------------------------------------
// 5) bias + |.| + LayerNorm + exact GELU   (warp per node, in place)
//    (phase cancels: (v cos p)^2 + (v sin p)^2 = v^2)
// ---------------------------------------------------------------------------
__global__ void final_kernel(float* __restrict__ out,
                             const float* __restrict__ bias,
                             const float* __restrict__ gamma,
                             const float* __restrict__ beta, int n) {
    int lane = threadIdx.x & 31;
    int wid = (blockIdx.x * blockDim.x + threadIdx.x) >> 5;
    int nw = (gridDim.x * blockDim.x) >> 5;
    float4 bv = *(const float4*)&bias[lane * 4];
    float4 gv = *(const float4*)&gamma[lane * 4];
    float4 tv = *(const float4*)&beta[lane * 4];
    for (int nid = wid; nid < n; nid += nw) {
        float4 v = *(const float4*)&out[nid * 128 + lane * 4];
        v.x += bv.x; v.y += bv.y; v.z += bv.z; v.w += bv.w;
        float4 m;
        m.x = sqrtf(v.x * v.x + 1e-12f);
        m.y = sqrtf(v.y * v.y + 1e-12f);
        m.z = sqrtf(v.z * v.z + 1e-12f);
        m.w = sqrtf(v.w * v.w + 1e-12f);
        float sum = m.x + m.y + m.z + m.w;
        float sq = m.x * m.x + m.y * m.y + m.z * m.z + m.w * m.w;
#pragma unroll
        for (int o = 16; o >= 1; o >>= 1) {
            sum += __shfl_xor_sync(0xFFFFFFFFu, sum, o);
            sq  += __shfl_xor_sync(0xFFFFFFFFu, sq, o);
        }
        float mu = sum * (1.0f / 128.0f);
        float var = sq * (1.0f / 128.0f) - mu * mu;
        float rstd = rsqrtf(var + 1e-5f);
        float4 r;
        float hx;
        hx = (m.x - mu) * rstd * gv.x + tv.x;
        r.x = 0.5f * hx * (1.0f + erff(hx * 0.70710678118654752f));
        hx = (m.y - mu) * rstd * gv.y + tv.y;
        r.y = 0.5f * hx * (1.0f + erff(hx * 0.70710678118654752f));
        hx = (m.z - mu) * rstd * gv.z + tv.z;
        r.z = 0.5f * hx * (1.0f + erff(hx * 0.70710678118654752f));
        hx = (m.w - mu) * rstd * gv.w + tv.w;
        r.w = 0.5f * hx * (1.0f + erff(hx * 0.70710678118654752f));
        *(float4*)&out[nid * 128 + lane * 4] = r;
    }
}

// ---------------------------------------------------------------------------
extern "C" void kernel_launch(void* const* d_in, const int* in_sizes, int n_in,
                              void* d_out, int out_size) {
    const float* x       = (const float*)d_in[0];
    const int*   ei      = (const int*)d_in[1];   // int32! (JAX x64 disabled)
    const float* W       = (const float*)d_in[2];
    const float* att_src = (const float*)d_in[3];
    const float* att_dst = (const float*)d_in[4];
    const float* bias    = (const float*)d_in[5];
    // d_in[6] = phase (mathematically cancels)
    const float* gamma   = (const float*)d_in[7];
    const float* beta    = (const float*)d_in[8];
    float* out = (float*)d_out;

    int n = in_sizes[0] / 128;
    int e = in_sizes[1] / 2;

    cudaFuncSetAttribute(gemm_kernel,
                         cudaFuncAttributeMaxDynamicSharedMemorySize, GEMM_SMEM);

    int nb_gemm = (n + 63) / 64;
    zero_kernel<<<1184, 256>>>(out, n);
    gemm_kernel<<<nb_gemm, 256, GEMM_SMEM>>>(x, W, n);
    attn_kernel<<<1184, 256>>>(att_src, att_dst, n);
    edge_pre_kernel<<<1184, 256>>>(ei, ei + e, e);
    edge_agg_kernel<<<2368, 256>>>(ei, ei + e, out, e);
    final_kernel<<<1184, 256>>>(out, bias, gamma, beta, n);
}

// round 10
// speedup vs baseline: 1.3249x; 1.3249x over previous
#include <cuda_runtime.h>
#include <math.h>

// Problem constants (fixed by the reference)
#define MAXN 100000
#define MAXE 1600000

// Scratch (device globals: allocation-free per harness rules).
__device__ __align__(16) float g_h[MAXN * 128];   // h = x @ W^T          (51.2 MB)
__device__ __align__(16) float g_ex[MAXE * 4];    // exp(leaky) per edge, CSR order
__device__ __align__(16) float g_asrc[MAXN * 4];  // a_src per node/head
__device__ __align__(16) float g_adst[MAXN * 4];  // a_dst per node/head
__device__ int g_srcs[MAXE];                      // src id per edge, CSR order
__device__ int g_cnt[MAXN];                       // in-degree
__device__ int g_off[MAXN];                       // CSR offsets (exclusive)
__device__ int g_woff[MAXN];                      // scatter cursors
__device__ int g_bsum[512];                       // block sums for scan

// ---------------------------------------------------------------------------
// 0) zero degree counters
// ---------------------------------------------------------------------------
__global__ void zero_cnt_kernel(int n) {
    int t = blockIdx.x * blockDim.x + threadIdx.x;
    int stride = gridDim.x * blockDim.x;
    for (int i = t; i < n; i += stride) g_cnt[i] = 0;
}

// ---------------------------------------------------------------------------
// 1) h = x @ W^T  (FP32, W staged transposed in smem, 64-row tiles)
// ---------------------------------------------------------------------------
#define GEMM_SMEM ((64 * 132 + 128 * 132) * 4)   // 101376 bytes

__global__ void gemm_kernel(const float* __restrict__ x,
                            const float* __restrict__ W, int n) {
    extern __shared__ float sm[];
    float* xs = sm;               // [64][132]
    float* ws = sm + 64 * 132;    // [128][132]  ws[k][col] = W[col][k]
    int tid = threadIdx.x;
    int row0 = blockIdx.x * 64;

    for (int idx = tid; idx < 128 * 128; idx += 256) {
        int col = idx & 127, k = idx >> 7;
        ws[k * 132 + col] = W[col * 128 + k];
    }
    for (int idx = tid; idx < 64 * 128; idx += 256) {
        int r = idx >> 7, k = idx & 127;
        int gr = row0 + r;
        xs[r * 132 + k] = (gr < n) ? x[gr * 128 + k] : 0.0f;
    }
    __syncthreads();

    const int tx = tid & 15;
    const int ty = tid >> 4;
    float acc[4][8];
#pragma unroll
    for (int i = 0; i < 4; i++)
#pragma unroll
        for (int j = 0; j < 8; j++) acc[i][j] = 0.0f;

#pragma unroll 8
    for (int k = 0; k < 128; k++) {
        float4 w0 = *(const float4*)(ws + k * 132 + tx * 8);
        float4 w1 = *(const float4*)(ws + k * 132 + tx * 8 + 4);
#pragma unroll
        for (int i = 0; i < 4; i++) {
            float xv = xs[(ty * 4 + i) * 132 + k];
            acc[i][0] += xv * w0.x; acc[i][1] += xv * w0.y;
            acc[i][2] += xv * w0.z; acc[i][3] += xv * w0.w;
            acc[i][4] += xv * w1.x; acc[i][5] += xv * w1.y;
            acc[i][6] += xv * w1.z; acc[i][7] += xv * w1.w;
        }
    }

#pragma unroll
    for (int i = 0; i < 4; i++) {
        int row = row0 + ty * 4 + i;
        if (row < n) {
            *(float4*)(g_h + row * 128 + tx * 8) =
                make_float4(acc[i][0], acc[i][1], acc[i][2], acc[i][3]);
            *(float4*)(g_h + row * 128 + tx * 8 + 4) =
                make_float4(acc[i][4], acc[i][5], acc[i][6], acc[i][7]);
        }
    }
}

// ---------------------------------------------------------------------------
// 2) a_src[n,h] = <h[n,h,:], att_src[h,:]>   (warp per node)
// ---------------------------------------------------------------------------
__global__ void attn_kernel(const float* __restrict__ att_src,
                            const float* __restrict__ att_dst, int n) {
    int lane = threadIdx.x & 31;
    int wid = (blockIdx.x * blockDim.x + threadIdx.x) >> 5;
    int nw = (gridDim.x * blockDim.x) >> 5;
    float4 as4 = *(const float4*)&att_src[lane * 4];
    float4 ad4 = *(const float4*)&att_dst[lane * 4];
    int head = lane >> 3;
    for (int nid = wid; nid < n; nid += nw) {
        float4 hv = *(const float4*)&g_h[nid * 128 + lane * 4];
        float ps = hv.x * as4.x + hv.y * as4.y + hv.z * as4.z + hv.w * as4.w;
        float pd = hv.x * ad4.x + hv.y * ad4.y + hv.z * ad4.z + hv.w * ad4.w;
#pragma unroll
        for (int o = 4; o >= 1; o >>= 1) {
            ps += __shfl_xor_sync(0xFFFFFFFFu, ps, o);
            pd += __shfl_xor_sync(0xFFFFFFFFu, pd, o);
        }
        if ((lane & 7) == 0) {
            g_asrc[nid * 4 + head] = ps;
            g_adst[nid * 4 + head] = pd;
        }
    }
}

// ---------------------------------------------------------------------------
// 3) CSR build: histogram of dst degrees
// ---------------------------------------------------------------------------
__global__ void hist_kernel(const int* __restrict__ dst, int e) {
    int t = blockIdx.x * blockDim.x + threadIdx.x;
    int stride = gridDim.x * blockDim.x;
    for (int i = t; i < e; i += stride) atomicAdd(&g_cnt[dst[i]], 1);
}

// 3a) per-256-chunk sums
__global__ void scan_block_kernel(int n) {
    __shared__ int sh[256];
    int t = threadIdx.x;
    int i = blockIdx.x * 256 + t;
    sh[t] = (i < n) ? g_cnt[i] : 0;
    __syncthreads();
    for (int o = 128; o > 0; o >>= 1) {
        if (t < o) sh[t] += sh[t + o];
        __syncthreads();
    }
    if (t == 0) g_bsum[blockIdx.x] = sh[0];
}

// 3b) exclusive scan over the (<=512) block sums, one block
__global__ void scan_top_kernel(int nb) {
    __shared__ int sh[512];
    int t = threadIdx.x;
    int v = (t < nb) ? g_bsum[t] : 0;
    sh[t] = v;
    __syncthreads();
    for (int o = 1; o < 512; o <<= 1) {
        int add = (t >= o) ? sh[t - o] : 0;
        __syncthreads();
        sh[t] += add;
        __syncthreads();
    }
    if (t < nb) g_bsum[t] = sh[t] - v;   // exclusive
}

// 3c) finalize per-element exclusive offsets + scatter cursors
__global__ void scan_final_kernel(int n) {
    __shared__ int sh[256];
    int t = threadIdx.x;
    int i = blockIdx.x * 256 + t;
    int v = (i < n) ? g_cnt[i] : 0;
    sh[t] = v;
    __syncthreads();
    for (int o = 1; o < 256; o <<= 1) {
        int add = (t >= o) ? sh[t - o] : 0;
        __syncthreads();
        sh[t] += add;
        __syncthreads();
    }
    if (i < n) {
        int excl = sh[t] - v + g_bsum[blockIdx.x];
        g_off[i] = excl;
        g_woff[i] = excl;
    }
}

// ---------------------------------------------------------------------------
// 4) scatter edges into CSR order; compute ex = exp(leaky_relu(logit)) here.
//    (segment-max skipped: softmax is shift-invariant, logits are O(5))
// ---------------------------------------------------------------------------
__global__ void scatter_kernel(const int* __restrict__ src,
                               const int* __restrict__ dst, int e) {
    int t = blockIdx.x * blockDim.x + threadIdx.x;
    int stride = gridDim.x * blockDim.x;
    for (int i = t; i < e; i += stride) {
        int s = src[i];
        int d = dst[i];
        float4 a = *(const float4*)&g_asrc[s * 4];
        float4 b = *(const float4*)&g_adst[d * 4];
        float t0 = a.x + b.x, t1 = a.y + b.y, t2 = a.z + b.z, t3 = a.w + b.w;
        float4 v;
        v.x = expf(t0 > 0.f ? t0 : 0.2f * t0);
        v.y = expf(t1 > 0.f ? t1 : 0.2f * t1);
        v.z = expf(t2 > 0.f ? t2 : 0.2f * t2);
        v.w = expf(t3 > 0.f ? t3 : 0.2f * t3);
        int pos = atomicAdd(&g_woff[d], 1);
        g_srcs[pos] = s;
        *(float4*)&g_ex[pos * 4] = v;
    }
}

// ---------------------------------------------------------------------------
// 5) fused aggregate + bias + |.| + LayerNorm + exact GELU  (warp per node)
//    No atomics: each warp owns one dst row; writes out exactly once.
//    (phase cancels: (v cos p)^2 + (v sin p)^2 = v^2)
// ---------------------------------------------------------------------------
__global__ void agg_kernel(const float* __restrict__ bias,
                           const float* __restrict__ gamma,
                           const float* __restrict__ beta,
                           float* __restrict__ out, int n) {
    int lane = threadIdx.x & 31;
    int wid = (blockIdx.x * blockDim.x + threadIdx.x) >> 5;
    int nw = (gridDim.x * blockDim.x) >> 5;
    int head = lane >> 3;
    float4 bv = *(const float4*)&bias[lane * 4];
    float4 gv = *(const float4*)&gamma[lane * 4];
    float4 tv = *(const float4*)&beta[lane * 4];

    for (int d = wid; d < n; d += nw) {
        int base = g_off[d];
        int deg = g_cnt[d];

        // pass 1: softmax denominators per head
        float4 s4 = make_float4(0.f, 0.f, 0.f, 0.f);
        for (int j = lane; j < deg; j += 32) {
            float4 exv = *(const float4*)&g_ex[(base + j) * 4];
            s4.x += exv.x; s4.y += exv.y; s4.z += exv.z; s4.w += exv.w;
        }
#pragma unroll
        for (int o = 16; o >= 1; o >>= 1) {
            s4.x += __shfl_xor_sync(0xFFFFFFFFu, s4.x, o);
            s4.y += __shfl_xor_sync(0xFFFFFFFFu, s4.y, o);
            s4.z += __shfl_xor_sync(0xFFFFFFFFu, s4.z, o);
            s4.w += __shfl_xor_sync(0xFFFFFFFFu, s4.w, o);
        }
        float sv = (head == 0) ? s4.x : (head == 1) ? s4.y : (head == 2) ? s4.z : s4.w;
        float rinv = 1.0f / (sv + 1e-16f);

        // pass 2: weighted accumulate of h[src]
        float4 acc = make_float4(0.f, 0.f, 0.f, 0.f);
        for (int j = 0; j < deg; j++) {
            int e = base + j;
            int s = g_srcs[e];                       // uniform across warp
            float alpha = g_ex[e * 4 + head] * rinv; // 4 distinct addrs/warp
            float4 hv = *(const float4*)&g_h[s * 128 + lane * 4];
            acc.x += hv.x * alpha; acc.y += hv.y * alpha;
            acc.z += hv.z * alpha; acc.w += hv.w * alpha;
        }

        // epilogue: bias, magnitude, LayerNorm, exact GELU
        float4 v;
        v.x = acc.x + bv.x; v.y = acc.y + bv.y;
        v.z = acc.z + bv.z; v.w = acc.w + bv.w;
        float4 m;
        m.x = sqrtf(v.x * v.x + 1e-12f);
        m.y = sqrtf(v.y * v.y + 1e-12f);
        m.z = sqrtf(v.z * v.z + 1e-12f);
        m.w = sqrtf(v.w * v.w + 1e-12f);
        float sum = m.x + m.y + m.z + m.w;
        float sq = m.x * m.x + m.y * m.y + m.z * m.z + m.w * m.w;
#pragma unroll
        for (int o = 16; o >= 1; o >>= 1) {
            sum += __shfl_xor_sync(0xFFFFFFFFu, sum, o);
            sq  += __shfl_xor_sync(0xFFFFFFFFu, sq, o);
        }
        float mu = sum * (1.0f / 128.0f);
        float var = sq * (1.0f / 128.0f) - mu * mu;
        float rstd = rsqrtf(var + 1e-5f);
        float4 r;
        float hx;
        hx = (m.x - mu) * rstd * gv.x + tv.x;
        r.x = 0.5f * hx * (1.0f + erff(hx * 0.70710678118654752f));
        hx = (m.y - mu) * rstd * gv.y + tv.y;
        r.y = 0.5f * hx * (1.0f + erff(hx * 0.70710678118654752f));
        hx = (m.z - mu) * rstd * gv.z + tv.z;
        r.z = 0.5f * hx * (1.0f + erff(hx * 0.70710678118654752f));
        hx = (m.w - mu) * rstd * gv.w + tv.w;
        r.w = 0.5f * hx * (1.0f + erff(hx * 0.70710678118654752f));
        *(float4*)&out[d * 128 + lane * 4] = r;
    }
}

// ---------------------------------------------------------------------------
extern "C" void kernel_launch(void* const* d_in, const int* in_sizes, int n_in,
                              void* d_out, int out_size) {
    const float* x       = (const float*)d_in[0];
    const int*   ei      = (const int*)d_in[1];   // int32 (JAX x64 disabled)
    const float* W       = (const float*)d_in[2];
    const float* att_src = (const float*)d_in[3];
    const float* att_dst = (const float*)d_in[4];
    const float* bias    = (const float*)d_in[5];
    // d_in[6] = phase (mathematically cancels)
    const float* gamma   = (const float*)d_in[7];
    const float* beta    = (const float*)d_in[8];
    float* out = (float*)d_out;

    int n = in_sizes[0] / 128;
    int e = in_sizes[1] / 2;
    const int* srcp = ei;
    const int* dstp = ei + e;
    int nb_scan = (n + 255) / 256;     // 391 for n=100000

    cudaFuncSetAttribute(gemm_kernel,
                         cudaFuncAttributeMaxDynamicSharedMemorySize, GEMM_SMEM);

    zero_cnt_kernel<<<296, 256>>>(n);
    gemm_kernel<<<(n + 63) / 64, 256, GEMM_SMEM>>>(x, W, n);
    attn_kernel<<<1184, 256>>>(att_src, att_dst, n);
    hist_kernel<<<1184, 256>>>(dstp, e);
    scan_block_kernel<<<nb_scan, 256>>>(n);
    scan_top_kernel<<<1, 512>>>(nb_scan);
    scan_final_kernel<<<nb_scan, 256>>>(n);
    scatter_kernel<<<1184, 256>>>(srcp, dstp, e);
    agg_kernel<<<2368, 256>>>(bias, gamma, beta, out, n);
}

// round 12
// speedup vs baseline: 1.9019x; 1.4355x over previous
#include <cuda_runtime.h>
#include <math.h>

// Problem constants (fixed by the reference)
#define MAXN 100000
#define MAXE 1600000

// Scratch (device globals: allocation-free per harness rules).
__device__ __align__(16) float g_h[MAXN * 128];   // h = x @ W^T          (51.2 MB)
__device__ __align__(16) float g_ex[MAXE * 4];    // exp(leaky) per edge, CSR order
__device__ __align__(16) float g_asrc[MAXN * 4];  // a_src per node/head
__device__ __align__(16) float g_adst[MAXN * 4];  // a_dst per node/head
__device__ __align__(16) float g_whi[128 * 128];  // tf32-hi of W, [k][col]
__device__ __align__(16) float g_wlo[128 * 128];  // tf32-lo of W, [k][col]
__device__ int g_srcs[MAXE];                      // src id per edge, CSR order
__device__ int g_cnt[MAXN];                       // in-degree
__device__ int g_off[MAXN];                       // CSR offsets (exclusive)
__device__ int g_woff[MAXN];                      // scatter cursors
__device__ int g_bsum[512];                       // block sums for scan

__device__ __forceinline__ unsigned f2tf32(float x) {
    unsigned r;
    asm("cvt.rna.tf32.f32 %0, %1;" : "=r"(r) : "f"(x));
    return r;
}

__device__ __forceinline__ void mma_tf32(float* c, const unsigned* a,
                                         unsigned b0, unsigned b1) {
    asm volatile(
        "mma.sync.aligned.m16n8k8.row.col.f32.tf32.tf32.f32 "
        "{%0,%1,%2,%3}, {%4,%5,%6,%7}, {%8,%9}, {%0,%1,%2,%3};"
        : "+f"(c[0]), "+f"(c[1]), "+f"(c[2]), "+f"(c[3])
        : "r"(a[0]), "r"(a[1]), "r"(a[2]), "r"(a[3]), "r"(b0), "r"(b1));
}

// ---------------------------------------------------------------------------
// 0) zero degree counters
// ---------------------------------------------------------------------------
__global__ void zero_cnt_kernel(int n) {
    int t = blockIdx.x * blockDim.x + threadIdx.x;
    int stride = gridDim.x * blockDim.x;
    for (int i = t; i < n; i += stride) g_cnt[i] = 0;
}

// ---------------------------------------------------------------------------
// 0b) split W into tf32 hi/lo, transposed to [k][col] layout
// ---------------------------------------------------------------------------
__global__ void wsplit_kernel(const float* __restrict__ W) {
    int idx = blockIdx.x * blockDim.x + threadIdx.x;
    if (idx < 128 * 128) {
        int col = idx >> 7, k = idx & 127;    // W[col][k]
        float v = W[idx];
        unsigned hi = f2tf32(v);
        float hif = __uint_as_float(hi);
        unsigned lo = f2tf32(v - hif);
        g_whi[k * 128 + col] = hif;
        g_wlo[k * 128 + col] = __uint_as_float(lo);
    }
}

// ---------------------------------------------------------------------------
// 1) h = x @ W^T via 3xTF32 mma.sync (fp32-accurate), attn fused in epilogue.
//    Block: 128 rows x 128 cols, K=128 all-resident. 8 warps, 16 rows each.
// ---------------------------------------------------------------------------
#define PADK 136
#define GEMM_SMEM ((3 * 128 * PADK) * 4)   // 208896 bytes

__global__ void __launch_bounds__(256, 1)
gemm_tf32_kernel(const float* __restrict__ x,
                 const float* __restrict__ att_src,
                 const float* __restrict__ att_dst, int n) {
    extern __shared__ float sm[];
    float* xs = sm;                       // [128][PADK] fp32 x rows
    float* wh = sm + 128 * PADK;          // [128][PADK] tf32-hi, [k][col]
    float* wl = sm + 2 * 128 * PADK;      // [128][PADK] tf32-lo
    int tid = threadIdx.x;
    int row0 = blockIdx.x * 128;

    // stage W hi/lo (coalesced, conflict-free float4 smem stores)
    for (int idx = tid; idx < 128 * 32; idx += 256) {
        int k = idx >> 5, c4 = (idx & 31) * 4;
        *(float4*)&wh[k * PADK + c4] = *(const float4*)&g_whi[k * 128 + c4];
        *(float4*)&wl[k * PADK + c4] = *(const float4*)&g_wlo[k * 128 + c4];
    }
    // stage x rows (zero-fill tail)
    for (int idx = tid; idx < 128 * 32; idx += 256) {
        int r = idx >> 5, c4 = (idx & 31) * 4;
        int gr = row0 + r;
        float4 v = (gr < n) ? *(const float4*)&x[gr * 128 + c4]
                            : make_float4(0.f, 0.f, 0.f, 0.f);
        *(float4*)&xs[r * PADK + c4] = v;
    }
    __syncthreads();

    int w = tid >> 5;            // warp id -> rows w*16 .. w*16+15
    int lane = tid & 31;
    int g = lane >> 2;           // group id (0..7)
    int tig = lane & 3;          // thread in group (0..3)
    int wrow = w * 16;

    float acc[16][4];
#pragma unroll
    for (int nt = 0; nt < 16; nt++)
#pragma unroll
        for (int j = 0; j < 4; j++) acc[nt][j] = 0.0f;

    for (int k0 = 0; k0 < 128; k0 += 8) {
        // A fragment (16x8), split hi/lo in registers
        float a0 = xs[(wrow + g) * PADK + k0 + tig];
        float a1 = xs[(wrow + g + 8) * PADK + k0 + tig];
        float a2 = xs[(wrow + g) * PADK + k0 + tig + 4];
        float a3 = xs[(wrow + g + 8) * PADK + k0 + tig + 4];
        unsigned ah[4], al[4];
        ah[0] = f2tf32(a0); al[0] = f2tf32(a0 - __uint_as_float(ah[0]));
        ah[1] = f2tf32(a1); al[1] = f2tf32(a1 - __uint_as_float(ah[1]));
        ah[2] = f2tf32(a2); al[2] = f2tf32(a2 - __uint_as_float(ah[2]));
        ah[3] = f2tf32(a3); al[3] = f2tf32(a3 - __uint_as_float(ah[3]));

        const float* whr0 = wh + (k0 + tig) * PADK + g;
        const float* whr1 = wh + (k0 + tig + 4) * PADK + g;
        const float* wlr0 = wl + (k0 + tig) * PADK + g;
        const float* wlr1 = wl + (k0 + tig + 4) * PADK + g;
#pragma unroll
        for (int nt = 0; nt < 16; nt++) {
            unsigned bh0 = __float_as_uint(whr0[nt * 8]);
            unsigned bh1 = __float_as_uint(whr1[nt * 8]);
            unsigned bl0 = __float_as_uint(wlr0[nt * 8]);
            unsigned bl1 = __float_as_uint(wlr1[nt * 8]);
            mma_tf32(acc[nt], ah, bh0, bh1);
            mma_tf32(acc[nt], al, bh0, bh1);
            mma_tf32(acc[nt], ah, bl0, bl1);
        }
    }

    // epilogue: store h + fused attention logits
    int r0 = row0 + wrow + g;
    int r1 = r0 + 8;
    float ps0[4] = {0.f, 0.f, 0.f, 0.f}, ps1[4] = {0.f, 0.f, 0.f, 0.f};
    float pd0[4] = {0.f, 0.f, 0.f, 0.f}, pd1[4] = {0.f, 0.f, 0.f, 0.f};
#pragma unroll
    for (int nt = 0; nt < 16; nt++) {
        int col = nt * 8 + tig * 2;
        int hh = nt >> 2;
        if (r0 < n) *(float2*)&g_h[r0 * 128 + col] = make_float2(acc[nt][0], acc[nt][1]);
        if (r1 < n) *(float2*)&g_h[r1 * 128 + col] = make_float2(acc[nt][2], acc[nt][3]);
        float as0 = att_src[col], as1 = att_src[col + 1];
        float ad0 = att_dst[col], ad1 = att_dst[col + 1];
        ps0[hh] += acc[nt][0] * as0 + acc[nt][1] * as1;
        ps1[hh] += acc[nt][2] * as0 + acc[nt][3] * as1;
        pd0[hh] += acc[nt][0] * ad0 + acc[nt][1] * ad1;
        pd1[hh] += acc[nt][2] * ad0 + acc[nt][3] * ad1;
    }
#pragma unroll
    for (int o = 1; o <= 2; o <<= 1) {
#pragma unroll
        for (int hh = 0; hh < 4; hh++) {
            ps0[hh] += __shfl_xor_sync(0xFFFFFFFFu, ps0[hh], o);
            ps1[hh] += __shfl_xor_sync(0xFFFFFFFFu, ps1[hh], o);
            pd0[hh] += __shfl_xor_sync(0xFFFFFFFFu, pd0[hh], o);
            pd1[hh] += __shfl_xor_sync(0xFFFFFFFFu, pd1[hh], o);
        }
    }
    if (tig == 0) {
        if (r0 < n) {
#pragma unroll
            for (int hh = 0; hh < 4; hh++) {
                g_asrc[r0 * 4 + hh] = ps0[hh];
                g_adst[r0 * 4 + hh] = pd0[hh];
            }
        }
        if (r1 < n) {
#pragma unroll
            for (int hh = 0; hh < 4; hh++) {
                g_asrc[r1 * 4 + hh] = ps1[hh];
                g_adst[r1 * 4 + hh] = pd1[hh];
            }
        }
    }
}

// ---------------------------------------------------------------------------
// 3) CSR build: histogram of dst degrees
// ---------------------------------------------------------------------------
__global__ void hist_kernel(const int* __restrict__ dst, int e) {
    int t = blockIdx.x * blockDim.x + threadIdx.x;
    int stride = gridDim.x * blockDim.x;
    for (int i = t; i < e; i += stride) atomicAdd(&g_cnt[dst[i]], 1);
}

// 3a) per-256-chunk sums
__global__ void scan_block_kernel(int n) {
    __shared__ int sh[256];
    int t = threadIdx.x;
    int i = blockIdx.x * 256 + t;
    sh[t] = (i < n) ? g_cnt[i] : 0;
    __syncthreads();
    for (int o = 128; o > 0; o >>= 1) {
        if (t < o) sh[t] += sh[t + o];
        __syncthreads();
    }
    if (t == 0) g_bsum[blockIdx.x] = sh[0];
}

// 3b) exclusive scan over the (<=512) block sums, one block
__global__ void scan_top_kernel(int nb) {
    __shared__ int sh[512];
    int t = threadIdx.x;
    int v = (t < nb) ? g_bsum[t] : 0;
    sh[t] = v;
    __syncthreads();
    for (int o = 1; o < 512; o <<= 1) {
        int add = (t >= o) ? sh[t - o] : 0;
        __syncthreads();
        sh[t] += add;
        __syncthreads();
    }
    if (t < nb) g_bsum[t] = sh[t] - v;   // exclusive
}

// 3c) finalize per-element exclusive offsets + scatter cursors
__global__ void scan_final_kernel(int n) {
    __shared__ int sh[256];
    int t = threadIdx.x;
    int i = blockIdx.x * 256 + t;
    int v = (i < n) ? g_cnt[i] : 0;
    sh[t] = v;
    __syncthreads();
    for (int o = 1; o < 256; o <<= 1) {
        int add = (t >= o) ? sh[t - o] : 0;
        __syncthreads();
        sh[t] += add;
        __syncthreads();
    }
    if (i < n) {
        int excl = sh[t] - v + g_bsum[blockIdx.x];
        g_off[i] = excl;
        g_woff[i] = excl;
    }
}

// ---------------------------------------------------------------------------
// 4) scatter edges into CSR order; compute ex = exp(leaky_relu(logit)) here.
//    (segment-max skipped: softmax is shift-invariant, logits are O(5))
// ---------------------------------------------------------------------------
__global__ void scatter_kernel(const int* __restrict__ src,
                               const int* __restrict__ dst, int e) {
    int t = blockIdx.x * blockDim.x + threadIdx.x;
    int stride = gridDim.x * blockDim.x;
    for (int i = t; i < e; i += stride) {
        int s = src[i];
        int d = dst[i];
        float4 a = *(const float4*)&g_asrc[s * 4];
        float4 b = *(const float4*)&g_adst[d * 4];
        float t0 = a.x + b.x, t1 = a.y + b.y, t2 = a.z + b.z, t3 = a.w + b.w;
        float4 v;
        v.x = expf(t0 > 0.f ? t0 : 0.2f * t0);
        v.y = expf(t1 > 0.f ? t1 : 0.2f * t1);
        v.z = expf(t2 > 0.f ? t2 : 0.2f * t2);
        v.w = expf(t3 > 0.f ? t3 : 0.2f * t3);
        int pos = atomicAdd(&g_woff[d], 1);
        g_srcs[pos] = s;
        *(float4*)&g_ex[pos * 4] = v;
    }
}

// ---------------------------------------------------------------------------
// 5) fused aggregate + bias + |.| + LayerNorm + exact GELU  (warp per node)
//    (phase cancels: (v cos p)^2 + (v sin p)^2 = v^2)
// ---------------------------------------------------------------------------
__global__ void agg_kernel(const float* __restrict__ bias,
                           const float* __restrict__ gamma,
                           const float* __restrict__ beta,
                           float* __restrict__ out, int n) {
    int lane = threadIdx.x & 31;
    int wid = (blockIdx.x * blockDim.x + threadIdx.x) >> 5;
    int nw = (gridDim.x * blockDim.x) >> 5;
    int head = lane >> 3;
    float4 bv = *(const float4*)&bias[lane * 4];
    float4 gv = *(const float4*)&gamma[lane * 4];
    float4 tv = *(const float4*)&beta[lane * 4];

    for (int d = wid; d < n; d += nw) {
        int base = g_off[d];
        int deg = g_cnt[d];

        // pass 1: softmax denominators per head
        float4 s4 = make_float4(0.f, 0.f, 0.f, 0.f);
        for (int j = lane; j < deg; j += 32) {
            float4 exv = *(const float4*)&g_ex[(base + j) * 4];
            s4.x += exv.x; s4.y += exv.y; s4.z += exv.z; s4.w += exv.w;
        }
#pragma unroll
        for (int o = 16; o >= 1; o >>= 1) {
            s4.x += __shfl_xor_sync(0xFFFFFFFFu, s4.x, o);
            s4.y += __shfl_xor_sync(0xFFFFFFFFu, s4.y, o);
            s4.z += __shfl_xor_sync(0xFFFFFFFFu, s4.z, o);
            s4.w += __shfl_xor_sync(0xFFFFFFFFu, s4.w, o);
        }
        float sv = (head == 0) ? s4.x : (head == 1) ? s4.y : (head == 2) ? s4.z : s4.w;
        float rinv = 1.0f / (sv + 1e-16f);

        // pass 2: weighted accumulate of h[src]
        float4 acc = make_float4(0.f, 0.f, 0.f, 0.f);
        for (int j = 0; j < deg; j++) {
            int e = base + j;
            int s = g_srcs[e];
            float alpha = g_ex[e * 4 + head] * rinv;
            float4 hv = *(const float4*)&g_h[s * 128 + lane * 4];
            acc.x += hv.x * alpha; acc.y += hv.y * alpha;
            acc.z += hv.z * alpha; acc.w += hv.w * alpha;
        }

        // epilogue: bias, magnitude, LayerNorm, exact GELU
        float4 v;
        v.x = acc.x + bv.x; v.y = acc.y + bv.y;
        v.z = acc.z + bv.z; v.w = acc.w + bv.w;
        float4 m;
        m.x = sqrtf(v.x * v.x + 1e-12f);
        m.y = sqrtf(v.y * v.y + 1e-12f);
        m.z = sqrtf(v.z * v.z + 1e-12f);
        m.w = sqrtf(v.w * v.w + 1e-12f);
        float sum = m.x + m.y + m.z + m.w;
        float sq = m.x * m.x + m.y * m.y + m.z * m.z + m.w * m.w;
#pragma unroll
        for (int o = 16; o >= 1; o >>= 1) {
            sum += __shfl_xor_sync(0xFFFFFFFFu, sum, o);
            sq  += __shfl_xor_sync(0xFFFFFFFFu, sq, o);
        }
        float mu = sum * (1.0f / 128.0f);
        float var = sq * (1.0f / 128.0f) - mu * mu;
        float rstd = rsqrtf(var + 1e-5f);
        float4 r;
        float hx;
        hx = (m.x - mu) * rstd * gv.x + tv.x;
        r.x = 0.5f * hx * (1.0f + erff(hx * 0.70710678118654752f));
        hx = (m.y - mu) * rstd * gv.y + tv.y;
        r.y = 0.5f * hx * (1.0f + erff(hx * 0.70710678118654752f));
        hx = (m.z - mu) * rstd * gv.z + tv.z;
        r.z = 0.5f * hx * (1.0f + erff(hx * 0.70710678118654752f));
        hx = (m.w - mu) * rstd * gv.w + tv.w;
        r.w = 0.5f * hx * (1.0f + erff(hx * 0.70710678118654752f));
        *(float4*)&out[d * 128 + lane * 4] = r;
    }
}

// ---------------------------------------------------------------------------
extern "C" void kernel_launch(void* const* d_in, const int* in_sizes, int n_in,
                              void* d_out, int out_size) {
    const float* x       = (const float*)d_in[0];
    const int*   ei      = (const int*)d_in[1];   // int32 (JAX x64 disabled)
    const float* W       = (const float*)d_in[2];
    const float* att_src = (const float*)d_in[3];
    const float* att_dst = (const float*)d_in[4];
    const float* bias    = (const float*)d_in[5];
    // d_in[6] = phase (mathematically cancels)
    const float* gamma   = (const float*)d_in[7];
    const float* beta    = (const float*)d_in[8];
    float* out = (float*)d_out;

    int n = in_sizes[0] / 128;
    int e = in_sizes[1] / 2;
    const int* srcp = ei;
    const int* dstp = ei + e;
    int nb_scan = (n + 255) / 256;

    cudaFuncSetAttribute(gemm_tf32_kernel,
                         cudaFuncAttributeMaxDynamicSharedMemorySize, GEMM_SMEM);

    zero_cnt_kernel<<<296, 256>>>(n);
    wsplit_kernel<<<64, 256>>>(W);
    gemm_tf32_kernel<<<(n + 127) / 128, 256, GEMM_SMEM>>>(x, att_src, att_dst, n);
    hist_kernel<<<1184, 256>>>(dstp, e);
    scan_block_kernel<<<nb_scan, 256>>>(n);
    scan_top_kernel<<<1, 512>>>(nb_scan);
    scan_final_kernel<<<nb_scan, 256>>>(n);
    scatter_kernel<<<1184, 256>>>(srcp, dstp, e);
    agg_kernel<<<2368, 256>>>(bias, gamma, beta, out, n);
}

// round 13
// speedup vs baseline: 2.1668x; 1.1393x over previous
#include <cuda_runtime.h>
#include <math.h>

// Problem constants (fixed by the reference)
#define MAXN 100000
#define MAXE 1600000

// Scratch (device globals: allocation-free per harness rules).
__device__ __align__(16) float g_h[MAXN * 128];   // h = x @ W^T          (51.2 MB)
__device__ __align__(16) float g_ex[MAXE * 4];    // exp(leaky) per edge, CSR order
__device__ __align__(16) float g_asrc[MAXN * 4];  // a_src per node/head
__device__ __align__(16) float g_adst[MAXN * 4];  // a_dst per node/head
__device__ __align__(16) float g_whi[128 * 128];  // tf32-hi of W, [k][col]
__device__ __align__(16) float g_wlo[128 * 128];  // tf32-lo of W, [k][col]
__device__ int g_srcs[MAXE];                      // src id per edge, CSR order
__device__ int g_cnt[MAXN];                       // in-degree
__device__ int g_off[MAXN];                       // CSR offsets (exclusive)
__device__ int g_woff[MAXN];                      // scatter cursors
__device__ int g_bsum[512];                       // block sums for scan

__device__ __forceinline__ unsigned f2tf32(float x) {
    unsigned r;
    asm("cvt.rna.tf32.f32 %0, %1;" : "=r"(r) : "f"(x));
    return r;
}

__device__ __forceinline__ void mma_tf32(float* c, const unsigned* a,
                                         unsigned b0, unsigned b1) {
    asm volatile(
        "mma.sync.aligned.m16n8k8.row.col.f32.tf32.tf32.f32 "
        "{%0,%1,%2,%3}, {%4,%5,%6,%7}, {%8,%9}, {%0,%1,%2,%3};"
        : "+f"(c[0]), "+f"(c[1]), "+f"(c[2]), "+f"(c[3])
        : "r"(a[0]), "r"(a[1]), "r"(a[2]), "r"(a[3]), "r"(b0), "r"(b1));
}

// ---------------------------------------------------------------------------
// 0) zero degree counters
// ---------------------------------------------------------------------------
__global__ void zero_cnt_kernel(int n) {
    int t = blockIdx.x * blockDim.x + threadIdx.x;
    int stride = gridDim.x * blockDim.x;
    for (int i = t; i < n; i += stride) g_cnt[i] = 0;
}

// ---------------------------------------------------------------------------
// 0b) split W into tf32 hi/lo, transposed to [k][col] layout
// ---------------------------------------------------------------------------
__global__ void wsplit_kernel(const float* __restrict__ W) {
    int idx = blockIdx.x * blockDim.x + threadIdx.x;
    if (idx < 128 * 128) {
        int col = idx >> 7, k = idx & 127;    // W[col][k]
        float v = W[idx];
        unsigned hi = f2tf32(v);
        float hif = __uint_as_float(hi);
        unsigned lo = f2tf32(v - hif);
        g_whi[k * 128 + col] = hif;
        g_wlo[k * 128 + col] = __uint_as_float(lo);
    }
}

// ---------------------------------------------------------------------------
// 1) h = x @ W^T via 3xTF32 mma.sync, attn logits fused in epilogue.
//    Block: 64 rows x 128 cols, 4 warps; warp tile 64x32 (4 m-tiles x 4 n-tiles).
//    Only x staged in smem (34 KB) -> 3 blocks/SM; W hi/lo read from L1/L2.
//    Warp w owns cols w*32..w*32+31 == head w exactly.
// ---------------------------------------------------------------------------
#define PADK 136
#define GEMM_SMEM (64 * PADK * 4)   // 34816 bytes

__global__ void __launch_bounds__(128)
gemm_tf32_kernel(const float* __restrict__ x,
                 const float* __restrict__ att_src,
                 const float* __restrict__ att_dst, int n) {
    extern __shared__ float xs[];     // [64][PADK]
    int tid = threadIdx.x;
    int row0 = blockIdx.x * 64;

    // stage x rows (zero-fill tail)
    for (int idx = tid; idx < 64 * 32; idx += 128) {
        int r = idx >> 5, c4 = (idx & 31) * 4;
        int gr = row0 + r;
        float4 v = (gr < n) ? *(const float4*)&x[gr * 128 + c4]
                            : make_float4(0.f, 0.f, 0.f, 0.f);
        *(float4*)&xs[r * PADK + c4] = v;
    }
    __syncthreads();

    int w = tid >> 5;             // warp id = head id = col block
    int lane = tid & 31;
    int g = lane >> 2;            // 0..7
    int tig = lane & 3;           // 0..3
    int colbase = w * 32;

    float acc[4][4][4] = {};      // [m-tile][n-tile][frag]

    for (int k0 = 0; k0 < 128; k0 += 8) {
        unsigned ah[4][4], al[4][4];
#pragma unroll
        for (int mt = 0; mt < 4; mt++) {
            int rb = (mt * 16 + g) * PADK + k0 + tig;
            float a0 = xs[rb];
            float a1 = xs[rb + 8 * PADK];
            float a2 = xs[rb + 4];
            float a3 = xs[rb + 8 * PADK + 4];
            ah[mt][0] = f2tf32(a0); al[mt][0] = f2tf32(a0 - __uint_as_float(ah[mt][0]));
            ah[mt][1] = f2tf32(a1); al[mt][1] = f2tf32(a1 - __uint_as_float(ah[mt][1]));
            ah[mt][2] = f2tf32(a2); al[mt][2] = f2tf32(a2 - __uint_as_float(ah[mt][2]));
            ah[mt][3] = f2tf32(a3); al[mt][3] = f2tf32(a3 - __uint_as_float(ah[mt][3]));
        }
#pragma unroll
        for (int nt = 0; nt < 4; nt++) {
            int col = colbase + nt * 8 + g;
            unsigned bh0 = __float_as_uint(g_whi[(k0 + tig) * 128 + col]);
            unsigned bh1 = __float_as_uint(g_whi[(k0 + tig + 4) * 128 + col]);
            unsigned bl0 = __float_as_uint(g_wlo[(k0 + tig) * 128 + col]);
            unsigned bl1 = __float_as_uint(g_wlo[(k0 + tig + 4) * 128 + col]);
#pragma unroll
            for (int mt = 0; mt < 4; mt++) {
                mma_tf32(acc[mt][nt], ah[mt], bh0, bh1);
                mma_tf32(acc[mt][nt], al[mt], bh0, bh1);
                mma_tf32(acc[mt][nt], ah[mt], bl0, bl1);
            }
        }
    }

    // epilogue: store h + fused attention logits for head w
    float as_c[4][2], ad_c[4][2];
#pragma unroll
    for (int nt = 0; nt < 4; nt++) {
        int col = colbase + nt * 8 + tig * 2;
        as_c[nt][0] = att_src[col]; as_c[nt][1] = att_src[col + 1];
        ad_c[nt][0] = att_dst[col]; ad_c[nt][1] = att_dst[col + 1];
    }
#pragma unroll
    for (int mt = 0; mt < 4; mt++) {
        int r0 = row0 + mt * 16 + g;
        int r1 = r0 + 8;
        float ps0 = 0.f, ps1 = 0.f, pd0 = 0.f, pd1 = 0.f;
#pragma unroll
        for (int nt = 0; nt < 4; nt++) {
            int cb = colbase + nt * 8 + tig * 2;
            if (r0 < n) *(float2*)&g_h[r0 * 128 + cb] =
                make_float2(acc[mt][nt][0], acc[mt][nt][1]);
            if (r1 < n) *(float2*)&g_h[r1 * 128 + cb] =
                make_float2(acc[mt][nt][2], acc[mt][nt][3]);
            ps0 += acc[mt][nt][0] * as_c[nt][0] + acc[mt][nt][1] * as_c[nt][1];
            ps1 += acc[mt][nt][2] * as_c[nt][0] + acc[mt][nt][3] * as_c[nt][1];
            pd0 += acc[mt][nt][0] * ad_c[nt][0] + acc[mt][nt][1] * ad_c[nt][1];
            pd1 += acc[mt][nt][2] * ad_c[nt][0] + acc[mt][nt][3] * ad_c[nt][1];
        }
        // reduce across the 4 lanes of each group (tig)
        ps0 += __shfl_xor_sync(0xFFFFFFFFu, ps0, 1);
        ps0 += __shfl_xor_sync(0xFFFFFFFFu, ps0, 2);
        ps1 += __shfl_xor_sync(0xFFFFFFFFu, ps1, 1);
        ps1 += __shfl_xor_sync(0xFFFFFFFFu, ps1, 2);
        pd0 += __shfl_xor_sync(0xFFFFFFFFu, pd0, 1);
        pd0 += __shfl_xor_sync(0xFFFFFFFFu, pd0, 2);
        pd1 += __shfl_xor_sync(0xFFFFFFFFu, pd1, 1);
        pd1 += __shfl_xor_sync(0xFFFFFFFFu, pd1, 2);
        if (tig == 0) {
            if (r0 < n) { g_asrc[r0 * 4 + w] = ps0; g_adst[r0 * 4 + w] = pd0; }
            if (r1 < n) { g_asrc[r1 * 4 + w] = ps1; g_adst[r1 * 4 + w] = pd1; }
        }
    }
}

// ---------------------------------------------------------------------------
// 3) CSR build: histogram of dst degrees
// ---------------------------------------------------------------------------
__global__ void hist_kernel(const int* __restrict__ dst, int e) {
    int t = blockIdx.x * blockDim.x + threadIdx.x;
    int stride = gridDim.x * blockDim.x;
    for (int i = t; i < e; i += stride) atomicAdd(&g_cnt[dst[i]], 1);
}

// 3a) per-256-chunk sums
__global__ void scan_block_kernel(int n) {
    __shared__ int sh[256];
    int t = threadIdx.x;
    int i = blockIdx.x * 256 + t;
    sh[t] = (i < n) ? g_cnt[i] : 0;
    __syncthreads();
    for (int o = 128; o > 0; o >>= 1) {
        if (t < o) sh[t] += sh[t + o];
        __syncthreads();
    }
    if (t == 0) g_bsum[blockIdx.x] = sh[0];
}

// 3b) exclusive scan over the (<=512) block sums, one block
__global__ void scan_top_kernel(int nb) {
    __shared__ int sh[512];
    int t = threadIdx.x;
    int v = (t < nb) ? g_bsum[t] : 0;
    sh[t] = v;
    __syncthreads();
    for (int o = 1; o < 512; o <<= 1) {
        int add = (t >= o) ? sh[t - o] : 0;
        __syncthreads();
        sh[t] += add;
        __syncthreads();
    }
    if (t < nb) g_bsum[t] = sh[t] - v;   // exclusive
}

// 3c) finalize per-element exclusive offsets + scatter cursors
__global__ void scan_final_kernel(int n) {
    __shared__ int sh[256];
    int t = threadIdx.x;
    int i = blockIdx.x * 256 + t;
    int v = (i < n) ? g_cnt[i] : 0;
    sh[t] = v;
    __syncthreads();
    for (int o = 1; o < 256; o <<= 1) {
        int add = (t >= o) ? sh[t - o] : 0;
        __syncthreads();
        sh[t] += add;
        __syncthreads();
    }
    if (i < n) {
        int excl = sh[t] - v + g_bsum[blockIdx.x];
        g_off[i] = excl;
        g_woff[i] = excl;
    }
}

// ---------------------------------------------------------------------------
// 4) scatter edges into CSR order; compute ex = exp(leaky_relu(logit)) here.
//    (segment-max skipped: softmax is shift-invariant, logits are O(5))
// ---------------------------------------------------------------------------
__global__ void scatter_kernel(const int* __restrict__ src,
                               const int* __restrict__ dst, int e) {
    int t = blockIdx.x * blockDim.x + threadIdx.x;
    int stride = gridDim.x * blockDim.x;
    for (int i = t; i < e; i += stride) {
        int s = src[i];
        int d = dst[i];
        float4 a = *(const float4*)&g_asrc[s * 4];
        float4 b = *(const float4*)&g_adst[d * 4];
        float t0 = a.x + b.x, t1 = a.y + b.y, t2 = a.z + b.z, t3 = a.w + b.w;
        float4 v;
        v.x = expf(t0 > 0.f ? t0 : 0.2f * t0);
        v.y = expf(t1 > 0.f ? t1 : 0.2f * t1);
        v.z = expf(t2 > 0.f ? t2 : 0.2f * t2);
        v.w = expf(t3 > 0.f ? t3 : 0.2f * t3);
        int pos = atomicAdd(&g_woff[d], 1);
        g_srcs[pos] = s;
        *(float4*)&g_ex[pos * 4] = v;
    }
}

// ---------------------------------------------------------------------------
// 5) fused aggregate + bias + |.| + LayerNorm + exact GELU  (warp per node)
//    pass 2 unrolled x4 for memory-level parallelism.
//    (phase cancels: (v cos p)^2 + (v sin p)^2 = v^2)
// ---------------------------------------------------------------------------
__global__ void agg_kernel(const float* __restrict__ bias,
                           const float* __restrict__ gamma,
                           const float* __restrict__ beta,
                           float* __restrict__ out, int n) {
    int lane = threadIdx.x & 31;
    int wid = (blockIdx.x * blockDim.x + threadIdx.x) >> 5;
    int nw = (gridDim.x * blockDim.x) >> 5;
    int head = lane >> 3;
    float4 bv = *(const float4*)&bias[lane * 4];
    float4 gv = *(const float4*)&gamma[lane * 4];
    float4 tv = *(const float4*)&beta[lane * 4];

    for (int d = wid; d < n; d += nw) {
        int base = g_off[d];
        int deg = g_cnt[d];

        // pass 1: softmax denominators per head
        float4 s4 = make_float4(0.f, 0.f, 0.f, 0.f);
        for (int j = lane; j < deg; j += 32) {
            float4 exv = *(const float4*)&g_ex[(base + j) * 4];
            s4.x += exv.x; s4.y += exv.y; s4.z += exv.z; s4.w += exv.w;
        }
#pragma unroll
        for (int o = 16; o >= 1; o >>= 1) {
            s4.x += __shfl_xor_sync(0xFFFFFFFFu, s4.x, o);
            s4.y += __shfl_xor_sync(0xFFFFFFFFu, s4.y, o);
            s4.z += __shfl_xor_sync(0xFFFFFFFFu, s4.z, o);
            s4.w += __shfl_xor_sync(0xFFFFFFFFu, s4.w, o);
        }
        float sv = (head == 0) ? s4.x : (head == 1) ? s4.y : (head == 2) ? s4.z : s4.w;
        float rinv = 1.0f / (sv + 1e-16f);

        // pass 2: weighted accumulate of h[src], unrolled x4 (MLP)
        float4 acc = make_float4(0.f, 0.f, 0.f, 0.f);
        int j = 0;
        int deg4 = deg & ~3;
        for (; j < deg4; j += 4) {
            int e0 = base + j;
            int s0 = g_srcs[e0], s1 = g_srcs[e0 + 1];
            int s2 = g_srcs[e0 + 2], s3 = g_srcs[e0 + 3];
            float a0 = g_ex[e0 * 4 + head];
            float a1 = g_ex[(e0 + 1) * 4 + head];
            float a2 = g_ex[(e0 + 2) * 4 + head];
            float a3 = g_ex[(e0 + 3) * 4 + head];
            float4 h0 = *(const float4*)&g_h[s0 * 128 + lane * 4];
            float4 h1 = *(const float4*)&g_h[s1 * 128 + lane * 4];
            float4 h2 = *(const float4*)&g_h[s2 * 128 + lane * 4];
            float4 h3 = *(const float4*)&g_h[s3 * 128 + lane * 4];
            a0 *= rinv; a1 *= rinv; a2 *= rinv; a3 *= rinv;
            acc.x += h0.x * a0 + h1.x * a1 + h2.x * a2 + h3.x * a3;
            acc.y += h0.y * a0 + h1.y * a1 + h2.y * a2 + h3.y * a3;
            acc.z += h0.z * a0 + h1.z * a1 + h2.z * a2 + h3.z * a3;
            acc.w += h0.w * a0 + h1.w * a1 + h2.w * a2 + h3.w * a3;
        }
        for (; j < deg; j++) {
            int e = base + j;
            int s = g_srcs[e];
            float alpha = g_ex[e * 4 + head] * rinv;
            float4 hv = *(const float4*)&g_h[s * 128 + lane * 4];
            acc.x += hv.x * alpha; acc.y += hv.y * alpha;
            acc.z += hv.z * alpha; acc.w += hv.w * alpha;
        }

        // epilogue: bias, magnitude, LayerNorm, exact GELU
        float4 v;
        v.x = acc.x + bv.x; v.y = acc.y + bv.y;
        v.z = acc.z + bv.z; v.w = acc.w + bv.w;
        float4 m;
        m.x = sqrtf(v.x * v.x + 1e-12f);
        m.y = sqrtf(v.y * v.y + 1e-12f);
        m.z = sqrtf(v.z * v.z + 1e-12f);
        m.w = sqrtf(v.w * v.w + 1e-12f);
        float sum = m.x + m.y + m.z + m.w;
        float sq = m.x * m.x + m.y * m.y + m.z * m.z + m.w * m.w;
#pragma unroll
        for (int o = 16; o >= 1; o >>= 1) {
            sum += __shfl_xor_sync(0xFFFFFFFFu, sum, o);
            sq  += __shfl_xor_sync(0xFFFFFFFFu, sq, o);
        }
        float mu = sum * (1.0f / 128.0f);
        float var = sq * (1.0f / 128.0f) - mu * mu;
        float rstd = rsqrtf(var + 1e-5f);
        float4 r;
        float hx;
        hx = (m.x - mu) * rstd * gv.x + tv.x;
        r.x = 0.5f * hx * (1.0f + erff(hx * 0.70710678118654752f));
        hx = (m.y - mu) * rstd * gv.y + tv.y;
        r.y = 0.5f * hx * (1.0f + erff(hx * 0.70710678118654752f));
        hx = (m.z - mu) * rstd * gv.z + tv.z;
        r.z = 0.5f * hx * (1.0f + erff(hx * 0.70710678118654752f));
        hx = (m.w - mu) * rstd * gv.w + tv.w;
        r.w = 0.5f * hx * (1.0f + erff(hx * 0.70710678118654752f));
        *(float4*)&out[d * 128 + lane * 4] = r;
    }
}

// ---------------------------------------------------------------------------
extern "C" void kernel_launch(void* const* d_in, const int* in_sizes, int n_in,
                              void* d_out, int out_size) {
    const float* x       = (const float*)d_in[0];
    const int*   ei      = (const int*)d_in[1];   // int32 (JAX x64 disabled)
    const float* W       = (const float*)d_in[2];
    const float* att_src = (const float*)d_in[3];
    const float* att_dst = (const float*)d_in[4];
    const float* bias    = (const float*)d_in[5];
    // d_in[6] = phase (mathematically cancels)
    const float* gamma   = (const float*)d_in[7];
    const float* beta    = (const float*)d_in[8];
    float* out = (float*)d_out;

    int n = in_sizes[0] / 128;
    int e = in_sizes[1] / 2;
    const int* srcp = ei;
    const int* dstp = ei + e;
    int nb_scan = (n + 255) / 256;

    zero_cnt_kernel<<<296, 256>>>(n);
    wsplit_kernel<<<64, 256>>>(W);
    gemm_tf32_kernel<<<(n + 63) / 64, 128, GEMM_SMEM>>>(x, att_src, att_dst, n);
    hist_kernel<<<1184, 256>>>(dstp, e);
    scan_block_kernel<<<nb_scan, 256>>>(n);
    scan_top_kernel<<<1, 512>>>(nb_scan);
    scan_final_kernel<<<nb_scan, 256>>>(n);
    scatter_kernel<<<1184, 256>>>(srcp, dstp, e);
    agg_kernel<<<2368, 256>>>(bias, gamma, beta, out, n);
}

// round 14
// speedup vs baseline: 2.5054x; 1.1563x over previous
#include <cuda_runtime.h>
#include <cuda_fp16.h>
#include <math.h>

// Problem constants (fixed by the reference)
#define MAXN 100000
#define MAXE 1600000

// Scratch (device globals: allocation-free per harness rules).
__device__ __align__(16) __half g_hh[MAXN * 128]; // h in fp16 (gather path, 25.6 MB)
__device__ __align__(16) float g_asrc[MAXN * 4];  // a_src per node/head
__device__ __align__(16) float g_adst[MAXN * 4];  // a_dst per node/head
__device__ __align__(16) float g_whi[128 * 128];  // tf32-hi of W, [k][col]
__device__ __align__(16) float g_wlo[128 * 128];  // tf32-lo of W, [k][col]
__device__ int g_srcs[MAXE];                      // src id per edge, CSR order
__device__ int g_cnt[MAXN];                       // in-degree
__device__ int g_off[MAXN];                       // CSR offsets (exclusive)
__device__ int g_woff[MAXN];                      // scatter cursors
__device__ int g_bsum[512];                       // block sums for scan

__device__ __forceinline__ unsigned f2tf32(float x) {
    unsigned r;
    asm("cvt.rna.tf32.f32 %0, %1;" : "=r"(r) : "f"(x));
    return r;
}

__device__ __forceinline__ void mma_tf32(float* c, const unsigned* a,
                                         unsigned b0, unsigned b1) {
    asm volatile(
        "mma.sync.aligned.m16n8k8.row.col.f32.tf32.tf32.f32 "
        "{%0,%1,%2,%3}, {%4,%5,%6,%7}, {%8,%9}, {%0,%1,%2,%3};"
        : "+f"(c[0]), "+f"(c[1]), "+f"(c[2]), "+f"(c[3])
        : "r"(a[0]), "r"(a[1]), "r"(a[2]), "r"(a[3]), "r"(b0), "r"(b1));
}

// ---------------------------------------------------------------------------
// 0) zero degree counters
// ---------------------------------------------------------------------------
__global__ void zero_cnt_kernel(int n) {
    int t = blockIdx.x * blockDim.x + threadIdx.x;
    int stride = gridDim.x * blockDim.x;
    for (int i = t; i < n; i += stride) g_cnt[i] = 0;
}

// ---------------------------------------------------------------------------
// 0b) split W into tf32 hi/lo, transposed to [k][col] layout
// ---------------------------------------------------------------------------
__global__ void wsplit_kernel(const float* __restrict__ W) {
    int idx = blockIdx.x * blockDim.x + threadIdx.x;
    if (idx < 128 * 128) {
        int col = idx >> 7, k = idx & 127;    // W[col][k]
        float v = W[idx];
        unsigned hi = f2tf32(v);
        float hif = __uint_as_float(hi);
        unsigned lo = f2tf32(v - hif);
        g_whi[k * 128 + col] = hif;
        g_wlo[k * 128 + col] = __uint_as_float(lo);
    }
}

// ---------------------------------------------------------------------------
// 1) h = x @ W^T via 3xTF32 mma.sync, attn logits fused in epilogue.
//    Block: 64 rows x 128 cols, 4 warps; warp tile 64x32.
//    h stored fp16 (only consumer is the gather in agg pass 2).
// ---------------------------------------------------------------------------
#define PADK 136
#define GEMM_SMEM (64 * PADK * 4)   // 34816 bytes

__global__ void __launch_bounds__(128, 4)
gemm_tf32_kernel(const float* __restrict__ x,
                 const float* __restrict__ att_src,
                 const float* __restrict__ att_dst, int n) {
    extern __shared__ float xs[];     // [64][PADK]
    int tid = threadIdx.x;
    int row0 = blockIdx.x * 64;

    // stage x rows (zero-fill tail)
    for (int idx = tid; idx < 64 * 32; idx += 128) {
        int r = idx >> 5, c4 = (idx & 31) * 4;
        int gr = row0 + r;
        float4 v = (gr < n) ? *(const float4*)&x[gr * 128 + c4]
                            : make_float4(0.f, 0.f, 0.f, 0.f);
        *(float4*)&xs[r * PADK + c4] = v;
    }
    __syncthreads();

    int w = tid >> 5;             // warp id = head id = col block
    int lane = tid & 31;
    int g = lane >> 2;            // 0..7
    int tig = lane & 3;           // 0..3
    int colbase = w * 32;

    float acc[4][4][4] = {};      // [m-tile][n-tile][frag]

    for (int k0 = 0; k0 < 128; k0 += 8) {
        unsigned ah[4][4], al[4][4];
#pragma unroll
        for (int mt = 0; mt < 4; mt++) {
            int rb = (mt * 16 + g) * PADK + k0 + tig;
            float a0 = xs[rb];
            float a1 = xs[rb + 8 * PADK];
            float a2 = xs[rb + 4];
            float a3 = xs[rb + 8 * PADK + 4];
            ah[mt][0] = f2tf32(a0); al[mt][0] = f2tf32(a0 - __uint_as_float(ah[mt][0]));
            ah[mt][1] = f2tf32(a1); al[mt][1] = f2tf32(a1 - __uint_as_float(ah[mt][1]));
            ah[mt][2] = f2tf32(a2); al[mt][2] = f2tf32(a2 - __uint_as_float(ah[mt][2]));
            ah[mt][3] = f2tf32(a3); al[mt][3] = f2tf32(a3 - __uint_as_float(ah[mt][3]));
        }
#pragma unroll
        for (int nt = 0; nt < 4; nt++) {
            int col = colbase + nt * 8 + g;
            unsigned bh0 = __float_as_uint(g_whi[(k0 + tig) * 128 + col]);
            unsigned bh1 = __float_as_uint(g_whi[(k0 + tig + 4) * 128 + col]);
            unsigned bl0 = __float_as_uint(g_wlo[(k0 + tig) * 128 + col]);
            unsigned bl1 = __float_as_uint(g_wlo[(k0 + tig + 4) * 128 + col]);
#pragma unroll
            for (int mt = 0; mt < 4; mt++) {
                mma_tf32(acc[mt][nt], ah[mt], bh0, bh1);
                mma_tf32(acc[mt][nt], al[mt], bh0, bh1);
                mma_tf32(acc[mt][nt], ah[mt], bl0, bl1);
            }
        }
    }

    // epilogue: store h (fp16) + fused attention logits for head w
    float as_c[4][2], ad_c[4][2];
#pragma unroll
    for (int nt = 0; nt < 4; nt++) {
        int col = colbase + nt * 8 + tig * 2;
        as_c[nt][0] = att_src[col]; as_c[nt][1] = att_src[col + 1];
        ad_c[nt][0] = att_dst[col]; ad_c[nt][1] = att_dst[col + 1];
    }
#pragma unroll
    for (int mt = 0; mt < 4; mt++) {
        int r0 = row0 + mt * 16 + g;
        int r1 = r0 + 8;
        float ps0 = 0.f, ps1 = 0.f, pd0 = 0.f, pd1 = 0.f;
#pragma unroll
        for (int nt = 0; nt < 4; nt++) {
            int cb = colbase + nt * 8 + tig * 2;
            if (r0 < n) *(__half2*)&g_hh[r0 * 128 + cb] =
                __float22half2_rn(make_float2(acc[mt][nt][0], acc[mt][nt][1]));
            if (r1 < n) *(__half2*)&g_hh[r1 * 128 + cb] =
                __float22half2_rn(make_float2(acc[mt][nt][2], acc[mt][nt][3]));
            ps0 += acc[mt][nt][0] * as_c[nt][0] + acc[mt][nt][1] * as_c[nt][1];
            ps1 += acc[mt][nt][2] * as_c[nt][0] + acc[mt][nt][3] * as_c[nt][1];
            pd0 += acc[mt][nt][0] * ad_c[nt][0] + acc[mt][nt][1] * ad_c[nt][1];
            pd1 += acc[mt][nt][2] * ad_c[nt][0] + acc[mt][nt][3] * ad_c[nt][1];
        }
        ps0 += __shfl_xor_sync(0xFFFFFFFFu, ps0, 1);
        ps0 += __shfl_xor_sync(0xFFFFFFFFu, ps0, 2);
        ps1 += __shfl_xor_sync(0xFFFFFFFFu, ps1, 1);
        ps1 += __shfl_xor_sync(0xFFFFFFFFu, ps1, 2);
        pd0 += __shfl_xor_sync(0xFFFFFFFFu, pd0, 1);
        pd0 += __shfl_xor_sync(0xFFFFFFFFu, pd0, 2);
        pd1 += __shfl_xor_sync(0xFFFFFFFFu, pd1, 1);
        pd1 += __shfl_xor_sync(0xFFFFFFFFu, pd1, 2);
        if (tig == 0) {
            if (r0 < n) { g_asrc[r0 * 4 + w] = ps0; g_adst[r0 * 4 + w] = pd0; }
            if (r1 < n) { g_asrc[r1 * 4 + w] = ps1; g_adst[r1 * 4 + w] = pd1; }
        }
    }
}

// ---------------------------------------------------------------------------
// 3) CSR build: histogram of dst degrees
// ---------------------------------------------------------------------------
__global__ void hist_kernel(const int* __restrict__ dst, int e) {
    int t = blockIdx.x * blockDim.x + threadIdx.x;
    int stride = gridDim.x * blockDim.x;
    for (int i = t; i < e; i += stride) atomicAdd(&g_cnt[dst[i]], 1);
}

// 3a) per-256-chunk sums
__global__ void scan_block_kernel(int n) {
    __shared__ int sh[256];
    int t = threadIdx.x;
    int i = blockIdx.x * 256 + t;
    sh[t] = (i < n) ? g_cnt[i] : 0;
    __syncthreads();
    for (int o = 128; o > 0; o >>= 1) {
        if (t < o) sh[t] += sh[t + o];
        __syncthreads();
    }
    if (t == 0) g_bsum[blockIdx.x] = sh[0];
}

// 3b) exclusive scan over the (<=512) block sums, one block
__global__ void scan_top_kernel(int nb) {
    __shared__ int sh[512];
    int t = threadIdx.x;
    int v = (t < nb) ? g_bsum[t] : 0;
    sh[t] = v;
    __syncthreads();
    for (int o = 1; o < 512; o <<= 1) {
        int add = (t >= o) ? sh[t - o] : 0;
        __syncthreads();
        sh[t] += add;
        __syncthreads();
    }
    if (t < nb) g_bsum[t] = sh[t] - v;   // exclusive
}

// 3c) finalize per-element exclusive offsets + scatter cursors
__global__ void scan_final_kernel(int n) {
    __shared__ int sh[256];
    int t = threadIdx.x;
    int i = blockIdx.x * 256 + t;
    int v = (i < n) ? g_cnt[i] : 0;
    sh[t] = v;
    __syncthreads();
    for (int o = 1; o < 256; o <<= 1) {
        int add = (t >= o) ? sh[t - o] : 0;
        __syncthreads();
        sh[t] += add;
        __syncthreads();
    }
    if (i < n) {
        int excl = sh[t] - v + g_bsum[blockIdx.x];
        g_off[i] = excl;
        g_woff[i] = excl;
    }
}

// ---------------------------------------------------------------------------
// 4) scatter edges into CSR order (src ids only; ex recomputed in agg)
// ---------------------------------------------------------------------------
__global__ void scatter_kernel(const int* __restrict__ src,
                               const int* __restrict__ dst, int e) {
    int t = blockIdx.x * blockDim.x + threadIdx.x;
    int stride = gridDim.x * blockDim.x;
    for (int i = t; i < e; i += stride) {
        int pos = atomicAdd(&g_woff[dst[i]], 1);
        g_srcs[pos] = src[i];
    }
}

// ---------------------------------------------------------------------------
// 5) fused aggregate + bias + |.| + LayerNorm + exact GELU  (warp per node)
//    ex recomputed from a_src/a_dst tables (1.6 MB, cache-resident);
//    identical computation in both passes keeps softmax consistent.
//    (segment-max skipped: softmax shift-invariant; phase cancels)
// ---------------------------------------------------------------------------
__global__ void agg_kernel(const float* __restrict__ bias,
                           const float* __restrict__ gamma,
                           const float* __restrict__ beta,
                           float* __restrict__ out, int n) {
    int lane = threadIdx.x & 31;
    int wid = (blockIdx.x * blockDim.x + threadIdx.x) >> 5;
    int nw = (gridDim.x * blockDim.x) >> 5;
    int head = lane >> 3;
    float4 bv = *(const float4*)&bias[lane * 4];
    float4 gv = *(const float4*)&gamma[lane * 4];
    float4 tv = *(const float4*)&beta[lane * 4];

    for (int d = wid; d < n; d += nw) {
        int base = g_off[d];
        int deg = g_cnt[d];
        float4 ad4 = *(const float4*)&g_adst[d * 4];

        // pass 1: softmax denominators per head (recomputed ex)
        float4 s4 = make_float4(0.f, 0.f, 0.f, 0.f);
        for (int j = lane; j < deg; j += 32) {
            int s = g_srcs[base + j];
            float4 a = *(const float4*)&g_asrc[s * 4];
            float t0 = a.x + ad4.x, t1 = a.y + ad4.y;
            float t2 = a.z + ad4.z, t3 = a.w + ad4.w;
            s4.x += expf(t0 > 0.f ? t0 : 0.2f * t0);
            s4.y += expf(t1 > 0.f ? t1 : 0.2f * t1);
            s4.z += expf(t2 > 0.f ? t2 : 0.2f * t2);
            s4.w += expf(t3 > 0.f ? t3 : 0.2f * t3);
        }
#pragma unroll
        for (int o = 16; o >= 1; o >>= 1) {
            s4.x += __shfl_xor_sync(0xFFFFFFFFu, s4.x, o);
            s4.y += __shfl_xor_sync(0xFFFFFFFFu, s4.y, o);
            s4.z += __shfl_xor_sync(0xFFFFFFFFu, s4.z, o);
            s4.w += __shfl_xor_sync(0xFFFFFFFFu, s4.w, o);
        }
        float sv = (head == 0) ? s4.x : (head == 1) ? s4.y : (head == 2) ? s4.z : s4.w;
        float rinv = 1.0f / (sv + 1e-16f);
        float adh = (head == 0) ? ad4.x : (head == 1) ? ad4.y : (head == 2) ? ad4.z : ad4.w;

        // pass 2: weighted accumulate of fp16 h[src], unrolled x4 (MLP)
        float4 acc = make_float4(0.f, 0.f, 0.f, 0.f);
        int j = 0;
        int deg4 = deg & ~3;
        for (; j < deg4; j += 4) {
            int e0 = base + j;
            int s0 = g_srcs[e0], s1 = g_srcs[e0 + 1];
            int s2 = g_srcs[e0 + 2], s3 = g_srcs[e0 + 3];
            float v0 = g_asrc[s0 * 4 + head] + adh;
            float v1 = g_asrc[s1 * 4 + head] + adh;
            float v2 = g_asrc[s2 * 4 + head] + adh;
            float v3 = g_asrc[s3 * 4 + head] + adh;
            __half2 p0 = *(const __half2*)&g_hh[s0 * 128 + lane * 4];
            __half2 q0 = *(const __half2*)&g_hh[s0 * 128 + lane * 4 + 2];
            __half2 p1 = *(const __half2*)&g_hh[s1 * 128 + lane * 4];
            __half2 q1 = *(const __half2*)&g_hh[s1 * 128 + lane * 4 + 2];
            __half2 p2 = *(const __half2*)&g_hh[s2 * 128 + lane * 4];
            __half2 q2 = *(const __half2*)&g_hh[s2 * 128 + lane * 4 + 2];
            __half2 p3 = *(const __half2*)&g_hh[s3 * 128 + lane * 4];
            __half2 q3 = *(const __half2*)&g_hh[s3 * 128 + lane * 4 + 2];
            float a0 = expf(v0 > 0.f ? v0 : 0.2f * v0) * rinv;
            float a1 = expf(v1 > 0.f ? v1 : 0.2f * v1) * rinv;
            float a2 = expf(v2 > 0.f ? v2 : 0.2f * v2) * rinv;
            float a3 = expf(v3 > 0.f ? v3 : 0.2f * v3) * rinv;
            float2 f;
            f = __half22float2(p0); acc.x += f.x * a0; acc.y += f.y * a0;
            f = __half22float2(q0); acc.z += f.x * a0; acc.w += f.y * a0;
            f = __half22float2(p1); acc.x += f.x * a1; acc.y += f.y * a1;
            f = __half22float2(q1); acc.z += f.x * a1; acc.w += f.y * a1;
            f = __half22float2(p2); acc.x += f.x * a2; acc.y += f.y * a2;
            f = __half22float2(q2); acc.z += f.x * a2; acc.w += f.y * a2;
            f = __half22float2(p3); acc.x += f.x * a3; acc.y += f.y * a3;
            f = __half22float2(q3); acc.z += f.x * a3; acc.w += f.y * a3;
        }
        for (; j < deg; j++) {
            int s = g_srcs[base + j];
            float v0 = g_asrc[s * 4 + head] + adh;
            float a0 = expf(v0 > 0.f ? v0 : 0.2f * v0) * rinv;
            __half2 p0 = *(const __half2*)&g_hh[s * 128 + lane * 4];
            __half2 q0 = *(const __half2*)&g_hh[s * 128 + lane * 4 + 2];
            float2 f;
            f = __half22float2(p0); acc.x += f.x * a0; acc.y += f.y * a0;
            f = __half22float2(q0); acc.z += f.x * a0; acc.w += f.y * a0;
        }

        // epilogue: bias, magnitude, LayerNorm, exact GELU
        float4 v;
        v.x = acc.x + bv.x; v.y = acc.y + bv.y;
        v.z = acc.z + bv.z; v.w = acc.w + bv.w;
        float4 m;
        m.x = sqrtf(v.x * v.x + 1e-12f);
        m.y = sqrtf(v.y * v.y + 1e-12f);
        m.z = sqrtf(v.z * v.z + 1e-12f);
        m.w = sqrtf(v.w * v.w + 1e-12f);
        float sum = m.x + m.y + m.z + m.w;
        float sq = m.x * m.x + m.y * m.y + m.z * m.z + m.w * m.w;
#pragma unroll
        for (int o = 16; o >= 1; o >>= 1) {
            sum += __shfl_xor_sync(0xFFFFFFFFu, sum, o);
            sq  += __shfl_xor_sync(0xFFFFFFFFu, sq, o);
        }
        float mu = sum * (1.0f / 128.0f);
        float var = sq * (1.0f / 128.0f) - mu * mu;
        float rstd = rsqrtf(var + 1e-5f);
        float4 r;
        float hx;
        hx = (m.x - mu) * rstd * gv.x + tv.x;
        r.x = 0.5f * hx * (1.0f + erff(hx * 0.70710678118654752f));
        hx = (m.y - mu) * rstd * gv.y + tv.y;
        r.y = 0.5f * hx * (1.0f + erff(hx * 0.70710678118654752f));
        hx = (m.z - mu) * rstd * gv.z + tv.z;
        r.z = 0.5f * hx * (1.0f + erff(hx * 0.70710678118654752f));
        hx = (m.w - mu) * rstd * gv.w + tv.w;
        r.w = 0.5f * hx * (1.0f + erff(hx * 0.70710678118654752f));
        *(float4*)&out[d * 128 + lane * 4] = r;
    }
}

// ---------------------------------------------------------------------------
extern "C" void kernel_launch(void* const* d_in, const int* in_sizes, int n_in,
                              void* d_out, int out_size) {
    const float* x       = (const float*)d_in[0];
    const int*   ei      = (const int*)d_in[1];   // int32 (JAX x64 disabled)
    const float* W       = (const float*)d_in[2];
    const float* att_src = (const float*)d_in[3];
    const float* att_dst = (const float*)d_in[4];
    const float* bias    = (const float*)d_in[5];
    // d_in[6] = phase (mathematically cancels)
    const float* gamma   = (const float*)d_in[7];
    const float* beta    = (const float*)d_in[8];
    float* out = (float*)d_out;

    int n = in_sizes[0] / 128;
    int e = in_sizes[1] / 2;
    const int* srcp = ei;
    const int* dstp = ei + e;
    int nb_scan = (n + 255) / 256;

    zero_cnt_kernel<<<296, 256>>>(n);
    wsplit_kernel<<<64, 256>>>(W);
    gemm_tf32_kernel<<<(n + 63) / 64, 128, GEMM_SMEM>>>(x, att_src, att_dst, n);
    hist_kernel<<<1184, 256>>>(dstp, e);
    scan_block_kernel<<<nb_scan, 256>>>(n);
    scan_top_kernel<<<1, 512>>>(nb_scan);
    scan_final_kernel<<<nb_scan, 256>>>(n);
    scatter_kernel<<<1184, 256>>>(srcp, dstp, e);
    agg_kernel<<<2368, 256>>>(bias, gamma, beta, out, n);
}

// round 15
// speedup vs baseline: 2.5904x; 1.0339x over previous
#include <cuda_runtime.h>
#include <cuda_fp16.h>
#include <math.h>

// Problem constants (fixed by the reference)
#define MAXN 100000
#define MAXE 1600000

// Scratch (device globals: allocation-free per harness rules).
__device__ __align__(16) __half g_hh[MAXN * 128]; // h in fp16 (gather path, 25.6 MB)
__device__ __align__(16) float g_asrc[MAXN * 4];  // a_src per node/head
__device__ __align__(16) float g_adst[MAXN * 4];  // a_dst per node/head
__device__ __align__(16) float g_whi[128 * 128];  // tf32-hi of W, [k][col]
__device__ __align__(16) float g_wlo[128 * 128];  // tf32-lo of W, [k][col]
__device__ int g_srcs[MAXE];                      // src id per edge, CSR order
__device__ int g_cnt[MAXN];                       // in-degree
__device__ int g_off[MAXN];                       // CSR offsets (exclusive)
__device__ int g_woff[MAXN];                      // scatter cursors
__device__ int g_bsum[512];                       // block sums for scan

__device__ __forceinline__ unsigned f2tf32(float x) {
    unsigned r;
    asm("cvt.rna.tf32.f32 %0, %1;" : "=r"(r) : "f"(x));
    return r;
}

__device__ __forceinline__ void mma_tf32(float* c, const unsigned* a,
                                         unsigned b0, unsigned b1) {
    asm volatile(
        "mma.sync.aligned.m16n8k8.row.col.f32.tf32.tf32.f32 "
        "{%0,%1,%2,%3}, {%4,%5,%6,%7}, {%8,%9}, {%0,%1,%2,%3};"
        : "+f"(c[0]), "+f"(c[1]), "+f"(c[2]), "+f"(c[3])
        : "r"(a[0]), "r"(a[1]), "r"(a[2]), "r"(a[3]), "r"(b0), "r"(b1));
}

// ---------------------------------------------------------------------------
// 0) zero degree counters
// ---------------------------------------------------------------------------
__global__ void zero_cnt_kernel(int n) {
    int t = blockIdx.x * blockDim.x + threadIdx.x;
    int stride = gridDim.x * blockDim.x;
    for (int i = t; i < n; i += stride) g_cnt[i] = 0;
}

// ---------------------------------------------------------------------------
// 0b) split W into tf32 hi/lo, transposed to [k][col] layout
// ---------------------------------------------------------------------------
__global__ void wsplit_kernel(const float* __restrict__ W) {
    int idx = blockIdx.x * blockDim.x + threadIdx.x;
    if (idx < 128 * 128) {
        int col = idx >> 7, k = idx & 127;    // W[col][k]
        float v = W[idx];
        unsigned hi = f2tf32(v);
        float hif = __uint_as_float(hi);
        unsigned lo = f2tf32(v - hif);
        g_whi[k * 128 + col] = hif;
        g_wlo[k * 128 + col] = __uint_as_float(lo);
    }
}

// ---------------------------------------------------------------------------
// 1) h = x @ W^T via 3xTF32 mma.sync, attn logits fused in epilogue.
//    Block: 64 rows x 128 cols, 4 warps; warp tile 64x32. h stored fp16.
// ---------------------------------------------------------------------------
#define PADK 136
#define GEMM_SMEM (64 * PADK * 4)   // 34816 bytes

__global__ void __launch_bounds__(128, 4)
gemm_tf32_kernel(const float* __restrict__ x,
                 const float* __restrict__ att_src,
                 const float* __restrict__ att_dst, int n) {
    extern __shared__ float xs[];     // [64][PADK]
    int tid = threadIdx.x;
    int row0 = blockIdx.x * 64;

    for (int idx = tid; idx < 64 * 32; idx += 128) {
        int r = idx >> 5, c4 = (idx & 31) * 4;
        int gr = row0 + r;
        float4 v = (gr < n) ? *(const float4*)&x[gr * 128 + c4]
                            : make_float4(0.f, 0.f, 0.f, 0.f);
        *(float4*)&xs[r * PADK + c4] = v;
    }
    __syncthreads();

    int w = tid >> 5;             // warp id = head id = col block
    int lane = tid & 31;
    int g = lane >> 2;            // 0..7
    int tig = lane & 3;           // 0..3
    int colbase = w * 32;

    float acc[4][4][4] = {};      // [m-tile][n-tile][frag]

    for (int k0 = 0; k0 < 128; k0 += 8) {
        unsigned ah[4][4], al[4][4];
#pragma unroll
        for (int mt = 0; mt < 4; mt++) {
            int rb = (mt * 16 + g) * PADK + k0 + tig;
            float a0 = xs[rb];
            float a1 = xs[rb + 8 * PADK];
            float a2 = xs[rb + 4];
            float a3 = xs[rb + 8 * PADK + 4];
            ah[mt][0] = f2tf32(a0); al[mt][0] = f2tf32(a0 - __uint_as_float(ah[mt][0]));
            ah[mt][1] = f2tf32(a1); al[mt][1] = f2tf32(a1 - __uint_as_float(ah[mt][1]));
            ah[mt][2] = f2tf32(a2); al[mt][2] = f2tf32(a2 - __uint_as_float(ah[mt][2]));
            ah[mt][3] = f2tf32(a3); al[mt][3] = f2tf32(a3 - __uint_as_float(ah[mt][3]));
        }
#pragma unroll
        for (int nt = 0; nt < 4; nt++) {
            int col = colbase + nt * 8 + g;
            unsigned bh0 = __float_as_uint(g_whi[(k0 + tig) * 128 + col]);
            unsigned bh1 = __float_as_uint(g_whi[(k0 + tig + 4) * 128 + col]);
            unsigned bl0 = __float_as_uint(g_wlo[(k0 + tig) * 128 + col]);
            unsigned bl1 = __float_as_uint(g_wlo[(k0 + tig + 4) * 128 + col]);
#pragma unroll
            for (int mt = 0; mt < 4; mt++) {
                mma_tf32(acc[mt][nt], ah[mt], bh0, bh1);
                mma_tf32(acc[mt][nt], al[mt], bh0, bh1);
                mma_tf32(acc[mt][nt], ah[mt], bl0, bl1);
            }
        }
    }

    // epilogue: store h (fp16) + fused attention logits for head w
    float as_c[4][2], ad_c[4][2];
#pragma unroll
    for (int nt = 0; nt < 4; nt++) {
        int col = colbase + nt * 8 + tig * 2;
        as_c[nt][0] = att_src[col]; as_c[nt][1] = att_src[col + 1];
        ad_c[nt][0] = att_dst[col]; ad_c[nt][1] = att_dst[col + 1];
    }
#pragma unroll
    for (int mt = 0; mt < 4; mt++) {
        int r0 = row0 + mt * 16 + g;
        int r1 = r0 + 8;
        float ps0 = 0.f, ps1 = 0.f, pd0 = 0.f, pd1 = 0.f;
#pragma unroll
        for (int nt = 0; nt < 4; nt++) {
            int cb = colbase + nt * 8 + tig * 2;
            if (r0 < n) *(__half2*)&g_hh[r0 * 128 + cb] =
                __float22half2_rn(make_float2(acc[mt][nt][0], acc[mt][nt][1]));
            if (r1 < n) *(__half2*)&g_hh[r1 * 128 + cb] =
                __float22half2_rn(make_float2(acc[mt][nt][2], acc[mt][nt][3]));
            ps0 += acc[mt][nt][0] * as_c[nt][0] + acc[mt][nt][1] * as_c[nt][1];
            ps1 += acc[mt][nt][2] * as_c[nt][0] + acc[mt][nt][3] * as_c[nt][1];
            pd0 += acc[mt][nt][0] * ad_c[nt][0] + acc[mt][nt][1] * ad_c[nt][1];
            pd1 += acc[mt][nt][2] * ad_c[nt][0] + acc[mt][nt][3] * ad_c[nt][1];
        }
        ps0 += __shfl_xor_sync(0xFFFFFFFFu, ps0, 1);
        ps0 += __shfl_xor_sync(0xFFFFFFFFu, ps0, 2);
        ps1 += __shfl_xor_sync(0xFFFFFFFFu, ps1, 1);
        ps1 += __shfl_xor_sync(0xFFFFFFFFu, ps1, 2);
        pd0 += __shfl_xor_sync(0xFFFFFFFFu, pd0, 1);
        pd0 += __shfl_xor_sync(0xFFFFFFFFu, pd0, 2);
        pd1 += __shfl_xor_sync(0xFFFFFFFFu, pd1, 1);
        pd1 += __shfl_xor_sync(0xFFFFFFFFu, pd1, 2);
        if (tig == 0) {
            if (r0 < n) { g_asrc[r0 * 4 + w] = ps0; g_adst[r0 * 4 + w] = pd0; }
            if (r1 < n) { g_asrc[r1 * 4 + w] = ps1; g_adst[r1 * 4 + w] = pd1; }
        }
    }
}

// ---------------------------------------------------------------------------
// 3) CSR build: histogram of dst degrees
// ---------------------------------------------------------------------------
__global__ void hist_kernel(const int* __restrict__ dst, int e) {
    int t = blockIdx.x * blockDim.x + threadIdx.x;
    int stride = gridDim.x * blockDim.x;
    for (int i = t; i < e; i += stride) atomicAdd(&g_cnt[dst[i]], 1);
}

// 3a) per-256-chunk sums
__global__ void scan_block_kernel(int n) {
    __shared__ int sh[256];
    int t = threadIdx.x;
    int i = blockIdx.x * 256 + t;
    sh[t] = (i < n) ? g_cnt[i] : 0;
    __syncthreads();
    for (int o = 128; o > 0; o >>= 1) {
        if (t < o) sh[t] += sh[t + o];
        __syncthreads();
    }
    if (t == 0) g_bsum[blockIdx.x] = sh[0];
}

// 3b) exclusive scan over the (<=512) block sums, one block
__global__ void scan_top_kernel(int nb) {
    __shared__ int sh[512];
    int t = threadIdx.x;
    int v = (t < nb) ? g_bsum[t] : 0;
    sh[t] = v;
    __syncthreads();
    for (int o = 1; o < 512; o <<= 1) {
        int add = (t >= o) ? sh[t - o] : 0;
        __syncthreads();
        sh[t] += add;
        __syncthreads();
    }
    if (t < nb) g_bsum[t] = sh[t] - v;   // exclusive
}

// 3c) finalize per-element exclusive offsets + scatter cursors
__global__ void scan_final_kernel(int n) {
    __shared__ int sh[256];
    int t = threadIdx.x;
    int i = blockIdx.x * 256 + t;
    int v = (i < n) ? g_cnt[i] : 0;
    sh[t] = v;
    __syncthreads();
    for (int o = 1; o < 256; o <<= 1) {
        int add = (t >= o) ? sh[t - o] : 0;
        __syncthreads();
        sh[t] += add;
        __syncthreads();
    }
    if (i < n) {
        int excl = sh[t] - v + g_bsum[blockIdx.x];
        g_off[i] = excl;
        g_woff[i] = excl;
    }
}

// ---------------------------------------------------------------------------
// 4) scatter edges into CSR order (src ids only; ex recomputed in agg)
// ---------------------------------------------------------------------------
__global__ void scatter_kernel(const int* __restrict__ src,
                               const int* __restrict__ dst, int e) {
    int t = blockIdx.x * blockDim.x + threadIdx.x;
    int stride = gridDim.x * blockDim.x;
    for (int i = t; i < e; i += stride) {
        int pos = atomicAdd(&g_woff[dst[i]], 1);
        g_srcs[pos] = src[i];
    }
}

// ---------------------------------------------------------------------------
// 5) fused aggregate + bias + |.| + LayerNorm + exact GELU  (warp per node)
//    ex recomputed from a_src/a_dst tables; pass 2 unrolled x8 (MLP).
// ---------------------------------------------------------------------------
__global__ void agg_kernel(const float* __restrict__ bias,
                           const float* __restrict__ gamma,
                           const float* __restrict__ beta,
                           float* __restrict__ out, int n) {
    int lane = threadIdx.x & 31;
    int wid = (blockIdx.x * blockDim.x + threadIdx.x) >> 5;
    int nw = (gridDim.x * blockDim.x) >> 5;
    int head = lane >> 3;
    float4 bv = *(const float4*)&bias[lane * 4];
    float4 gv = *(const float4*)&gamma[lane * 4];
    float4 tv = *(const float4*)&beta[lane * 4];

    for (int d = wid; d < n; d += nw) {
        int base = g_off[d];
        int deg = g_cnt[d];
        float4 ad4 = *(const float4*)&g_adst[d * 4];

        // pass 1: softmax denominators per head (recomputed ex)
        float4 s4 = make_float4(0.f, 0.f, 0.f, 0.f);
        for (int j = lane; j < deg; j += 32) {
            int s = g_srcs[base + j];
            float4 a = *(const float4*)&g_asrc[s * 4];
            float t0 = a.x + ad4.x, t1 = a.y + ad4.y;
            float t2 = a.z + ad4.z, t3 = a.w + ad4.w;
            s4.x += expf(t0 > 0.f ? t0 : 0.2f * t0);
            s4.y += expf(t1 > 0.f ? t1 : 0.2f * t1);
            s4.z += expf(t2 > 0.f ? t2 : 0.2f * t2);
            s4.w += expf(t3 > 0.f ? t3 : 0.2f * t3);
        }
#pragma unroll
        for (int o = 16; o >= 1; o >>= 1) {
            s4.x += __shfl_xor_sync(0xFFFFFFFFu, s4.x, o);
            s4.y += __shfl_xor_sync(0xFFFFFFFFu, s4.y, o);
            s4.z += __shfl_xor_sync(0xFFFFFFFFu, s4.z, o);
            s4.w += __shfl_xor_sync(0xFFFFFFFFu, s4.w, o);
        }
        float sv = (head == 0) ? s4.x : (head == 1) ? s4.y : (head == 2) ? s4.z : s4.w;
        float rinv = 1.0f / (sv + 1e-16f);
        float adh = (head == 0) ? ad4.x : (head == 1) ? ad4.y : (head == 2) ? ad4.z : ad4.w;

        // pass 2: weighted accumulate of fp16 h[src], unrolled x8 (MLP)
        float4 acc = make_float4(0.f, 0.f, 0.f, 0.f);
        int j = 0;
        int deg8 = deg & ~7;
        for (; j < deg8; j += 8) {
            int e0 = base + j;
            int si[8];
            float vi[8];
            __half2 ph[8], qh[8];
#pragma unroll
            for (int u = 0; u < 8; u++) si[u] = g_srcs[e0 + u];
#pragma unroll
            for (int u = 0; u < 8; u++) {
                vi[u] = g_asrc[si[u] * 4 + head] + adh;
                ph[u] = *(const __half2*)&g_hh[si[u] * 128 + lane * 4];
                qh[u] = *(const __half2*)&g_hh[si[u] * 128 + lane * 4 + 2];
            }
#pragma unroll
            for (int u = 0; u < 8; u++) {
                float a0 = expf(vi[u] > 0.f ? vi[u] : 0.2f * vi[u]) * rinv;
                float2 f;
                f = __half22float2(ph[u]); acc.x += f.x * a0; acc.y += f.y * a0;
                f = __half22float2(qh[u]); acc.z += f.x * a0; acc.w += f.y * a0;
            }
        }
        for (; j < deg; j++) {
            int s = g_srcs[base + j];
            float v0 = g_asrc[s * 4 + head] + adh;
            float a0 = expf(v0 > 0.f ? v0 : 0.2f * v0) * rinv;
            __half2 p0 = *(const __half2*)&g_hh[s * 128 + lane * 4];
            __half2 q0 = *(const __half2*)&g_hh[s * 128 + lane * 4 + 2];
            float2 f;
            f = __half22float2(p0); acc.x += f.x * a0; acc.y += f.y * a0;
            f = __half22float2(q0); acc.z += f.x * a0; acc.w += f.y * a0;
        }

        // epilogue: bias, magnitude, LayerNorm, exact GELU
        float4 v;
        v.x = acc.x + bv.x; v.y = acc.y + bv.y;
        v.z = acc.z + bv.z; v.w = acc.w + bv.w;
        float4 m;
        m.x = sqrtf(v.x * v.x + 1e-12f);
        m.y = sqrtf(v.y * v.y + 1e-12f);
        m.z = sqrtf(v.z * v.z + 1e-12f);
        m.w = sqrtf(v.w * v.w + 1e-12f);
        float sum = m.x + m.y + m.z + m.w;
        float sq = m.x * m.x + m.y * m.y + m.z * m.z + m.w * m.w;
#pragma unroll
        for (int o = 16; o >= 1; o >>= 1) {
            sum += __shfl_xor_sync(0xFFFFFFFFu, sum, o);
            sq  += __shfl_xor_sync(0xFFFFFFFFu, sq, o);
        }
        float mu = sum * (1.0f / 128.0f);
        float var = sq * (1.0f / 128.0f) - mu * mu;
        float rstd = rsqrtf(var + 1e-5f);
        float4 r;
        float hx;
        hx = (m.x - mu) * rstd * gv.x + tv.x;
        r.x = 0.5f * hx * (1.0f + erff(hx * 0.70710678118654752f));
        hx = (m.y - mu) * rstd * gv.y + tv.y;
        r.y = 0.5f * hx * (1.0f + erff(hx * 0.70710678118654752f));
        hx = (m.z - mu) * rstd * gv.z + tv.z;
        r.z = 0.5f * hx * (1.0f + erff(hx * 0.70710678118654752f));
        hx = (m.w - mu) * rstd * gv.w + tv.w;
        r.w = 0.5f * hx * (1.0f + erff(hx * 0.70710678118654752f));
        *(float4*)&out[d * 128 + lane * 4] = r;
    }
}

// ---------------------------------------------------------------------------
// Launch: fork CSR build (edge-only deps) parallel to wsplit+gemm (x/W deps),
// join before agg. Streams/events created per invocation — kernel_launch only
// runs during the correctness call and graph capture, never during replays.
// ---------------------------------------------------------------------------
extern "C" void kernel_launch(void* const* d_in, const int* in_sizes, int n_in,
                              void* d_out, int out_size) {
    const float* x       = (const float*)d_in[0];
    const int*   ei      = (const int*)d_in[1];   // int32 (JAX x64 disabled)
    const float* W       = (const float*)d_in[2];
    const float* att_src = (const float*)d_in[3];
    const float* att_dst = (const float*)d_in[4];
    const float* bias    = (const float*)d_in[5];
    // d_in[6] = phase (mathematically cancels)
    const float* gamma   = (const float*)d_in[7];
    const float* beta    = (const float*)d_in[8];
    float* out = (float*)d_out;

    int n = in_sizes[0] / 128;
    int e = in_sizes[1] / 2;
    const int* srcp = ei;
    const int* dstp = ei + e;
    int nb_scan = (n + 255) / 256;

    cudaStream_t s2;
    cudaEvent_t ev_fork, ev_join;
    cudaStreamCreateWithFlags(&s2, cudaStreamNonBlocking);
    cudaEventCreateWithFlags(&ev_fork, cudaEventDisableTiming);
    cudaEventCreateWithFlags(&ev_join, cudaEventDisableTiming);

    // fork: CSR chain on s2 (depends only on edge_index)
    cudaEventRecord(ev_fork, 0);
    cudaStreamWaitEvent(s2, ev_fork, 0);
    zero_cnt_kernel<<<296, 256, 0, s2>>>(n);
    hist_kernel<<<1184, 256, 0, s2>>>(dstp, e);
    scan_block_kernel<<<nb_scan, 256, 0, s2>>>(n);
    scan_top_kernel<<<1, 512, 0, s2>>>(nb_scan);
    scan_final_kernel<<<nb_scan, 256, 0, s2>>>(n);
    scatter_kernel<<<1184, 256, 0, s2>>>(srcp, dstp, e);
    cudaEventRecord(ev_join, s2);

    // main stream: GEMM chain (depends only on x, W, att)
    wsplit_kernel<<<64, 256>>>(W);
    gemm_tf32_kernel<<<(n + 63) / 64, 128, GEMM_SMEM>>>(x, att_src, att_dst, n);

    // join: agg needs both branches
    cudaStreamWaitEvent(0, ev_join, 0);
    agg_kernel<<<2368, 256>>>(bias, gamma, beta, out, n);
}

// round 16
// speedup vs baseline: 2.7486x; 1.0611x over previous
#include <cuda_runtime.h>
#include <cuda_fp16.h>
#include <math.h>

// Problem constants (fixed by the reference)
#define MAXN 100000
#define MAXE 1600000

// Scratch (device globals: allocation-free per harness rules).
__device__ __align__(16) __half g_hh[MAXN * 128]; // h in fp16 (gather path, 25.6 MB)
__device__ __align__(16) float g_asrc[MAXN * 4];  // a_src per node/head
__device__ __align__(16) float g_adst[MAXN * 4];  // a_dst per node/head
__device__ __align__(16) float g_whi[128 * 128];  // tf32-hi of W, [k][col]
__device__ __align__(16) float g_wlo[128 * 128];  // tf32-lo of W, [k][col]
__device__ int g_srcs[MAXE];                      // src id per edge, CSR order
__device__ int g_cnt[MAXN];                       // in-degree
__device__ int g_off[MAXN];                       // CSR offsets (exclusive)
__device__ int g_woff[MAXN];                      // scatter cursors
__device__ int g_bsum[512];                       // block sums for scan

__device__ __forceinline__ unsigned f2tf32(float x) {
    unsigned r;
    asm("cvt.rna.tf32.f32 %0, %1;" : "=r"(r) : "f"(x));
    return r;
}

__device__ __forceinline__ void mma_tf32(float* c, const unsigned* a,
                                         unsigned b0, unsigned b1) {
    asm volatile(
        "mma.sync.aligned.m16n8k8.row.col.f32.tf32.tf32.f32 "
        "{%0,%1,%2,%3}, {%4,%5,%6,%7}, {%8,%9}, {%0,%1,%2,%3};"
        : "+f"(c[0]), "+f"(c[1]), "+f"(c[2]), "+f"(c[3])
        : "r"(a[0]), "r"(a[1]), "r"(a[2]), "r"(a[3]), "r"(b0), "r"(b1));
}

// ---------------------------------------------------------------------------
// 0) zero degree counters
// ---------------------------------------------------------------------------
__global__ void zero_cnt_kernel(int n) {
    int t = blockIdx.x * blockDim.x + threadIdx.x;
    int stride = gridDim.x * blockDim.x;
    for (int i = t; i < n; i += stride) g_cnt[i] = 0;
}

// ---------------------------------------------------------------------------
// 0b) split W into tf32 hi/lo, transposed to [k][col] layout
// ---------------------------------------------------------------------------
__global__ void wsplit_kernel(const float* __restrict__ W) {
    int idx = blockIdx.x * blockDim.x + threadIdx.x;
    if (idx < 128 * 128) {
        int col = idx >> 7, k = idx & 127;    // W[col][k]
        float v = W[idx];
        unsigned hi = f2tf32(v);
        float hif = __uint_as_float(hi);
        unsigned lo = f2tf32(v - hif);
        g_whi[k * 128 + col] = hif;
        g_wlo[k * 128 + col] = __uint_as_float(lo);
    }
}

// ---------------------------------------------------------------------------
// 1) h = x @ W^T via 3xTF32 mma.sync, attn logits fused in epilogue.
//    Block: 64 rows x 128 cols, 4 warps; warp tile 64x32. h stored fp16.
// ---------------------------------------------------------------------------
#define PADK 136
#define GEMM_SMEM (64 * PADK * 4)   // 34816 bytes

__global__ void __launch_bounds__(128, 4)
gemm_tf32_kernel(const float* __restrict__ x,
                 const float* __restrict__ att_src,
                 const float* __restrict__ att_dst, int n) {
    extern __shared__ float xs[];     // [64][PADK]
    int tid = threadIdx.x;
    int row0 = blockIdx.x * 64;

    for (int idx = tid; idx < 64 * 32; idx += 128) {
        int r = idx >> 5, c4 = (idx & 31) * 4;
        int gr = row0 + r;
        float4 v = (gr < n) ? *(const float4*)&x[gr * 128 + c4]
                            : make_float4(0.f, 0.f, 0.f, 0.f);
        *(float4*)&xs[r * PADK + c4] = v;
    }
    __syncthreads();

    int w = tid >> 5;             // warp id = head id = col block
    int lane = tid & 31;
    int g = lane >> 2;            // 0..7
    int tig = lane & 3;           // 0..3
    int colbase = w * 32;

    float acc[4][4][4] = {};      // [m-tile][n-tile][frag]

    for (int k0 = 0; k0 < 128; k0 += 8) {
        unsigned ah[4][4], al[4][4];
#pragma unroll
        for (int mt = 0; mt < 4; mt++) {
            int rb = (mt * 16 + g) * PADK + k0 + tig;
            float a0 = xs[rb];
            float a1 = xs[rb + 8 * PADK];
            float a2 = xs[rb + 4];
            float a3 = xs[rb + 8 * PADK + 4];
            ah[mt][0] = f2tf32(a0); al[mt][0] = f2tf32(a0 - __uint_as_float(ah[mt][0]));
            ah[mt][1] = f2tf32(a1); al[mt][1] = f2tf32(a1 - __uint_as_float(ah[mt][1]));
            ah[mt][2] = f2tf32(a2); al[mt][2] = f2tf32(a2 - __uint_as_float(ah[mt][2]));
            ah[mt][3] = f2tf32(a3); al[mt][3] = f2tf32(a3 - __uint_as_float(ah[mt][3]));
        }
#pragma unroll
        for (int nt = 0; nt < 4; nt++) {
            int col = colbase + nt * 8 + g;
            unsigned bh0 = __float_as_uint(g_whi[(k0 + tig) * 128 + col]);
            unsigned bh1 = __float_as_uint(g_whi[(k0 + tig + 4) * 128 + col]);
            unsigned bl0 = __float_as_uint(g_wlo[(k0 + tig) * 128 + col]);
            unsigned bl1 = __float_as_uint(g_wlo[(k0 + tig + 4) * 128 + col]);
#pragma unroll
            for (int mt = 0; mt < 4; mt++) {
                mma_tf32(acc[mt][nt], ah[mt], bh0, bh1);
                mma_tf32(acc[mt][nt], al[mt], bh0, bh1);
                mma_tf32(acc[mt][nt], ah[mt], bl0, bl1);
            }
        }
    }

    // epilogue: store h (fp16) + fused attention logits for head w
    float as_c[4][2], ad_c[4][2];
#pragma unroll
    for (int nt = 0; nt < 4; nt++) {
        int col = colbase + nt * 8 + tig * 2;
        as_c[nt][0] = att_src[col]; as_c[nt][1] = att_src[col + 1];
        ad_c[nt][0] = att_dst[col]; ad_c[nt][1] = att_dst[col + 1];
    }
#pragma unroll
    for (int mt = 0; mt < 4; mt++) {
        int r0 = row0 + mt * 16 + g;
        int r1 = r0 + 8;
        float ps0 = 0.f, ps1 = 0.f, pd0 = 0.f, pd1 = 0.f;
#pragma unroll
        for (int nt = 0; nt < 4; nt++) {
            int cb = colbase + nt * 8 + tig * 2;
            if (r0 < n) *(__half2*)&g_hh[r0 * 128 + cb] =
                __float22half2_rn(make_float2(acc[mt][nt][0], acc[mt][nt][1]));
            if (r1 < n) *(__half2*)&g_hh[r1 * 128 + cb] =
                __float22half2_rn(make_float2(acc[mt][nt][2], acc[mt][nt][3]));
            ps0 += acc[mt][nt][0] * as_c[nt][0] + acc[mt][nt][1] * as_c[nt][1];
            ps1 += acc[mt][nt][2] * as_c[nt][0] + acc[mt][nt][3] * as_c[nt][1];
            pd0 += acc[mt][nt][0] * ad_c[nt][0] + acc[mt][nt][1] * ad_c[nt][1];
            pd1 += acc[mt][nt][2] * ad_c[nt][0] + acc[mt][nt][3] * ad_c[nt][1];
        }
        ps0 += __shfl_xor_sync(0xFFFFFFFFu, ps0, 1);
        ps0 += __shfl_xor_sync(0xFFFFFFFFu, ps0, 2);
        ps1 += __shfl_xor_sync(0xFFFFFFFFu, ps1, 1);
        ps1 += __shfl_xor_sync(0xFFFFFFFFu, ps1, 2);
        pd0 += __shfl_xor_sync(0xFFFFFFFFu, pd0, 1);
        pd0 += __shfl_xor_sync(0xFFFFFFFFu, pd0, 2);
        pd1 += __shfl_xor_sync(0xFFFFFFFFu, pd1, 1);
        pd1 += __shfl_xor_sync(0xFFFFFFFFu, pd1, 2);
        if (tig == 0) {
            if (r0 < n) { g_asrc[r0 * 4 + w] = ps0; g_adst[r0 * 4 + w] = pd0; }
            if (r1 < n) { g_asrc[r1 * 4 + w] = ps1; g_adst[r1 * 4 + w] = pd1; }
        }
    }
}

// ---------------------------------------------------------------------------
// 3) CSR build: histogram of dst degrees
// ---------------------------------------------------------------------------
__global__ void hist_kernel(const int* __restrict__ dst, int e) {
    int t = blockIdx.x * blockDim.x + threadIdx.x;
    int stride = gridDim.x * blockDim.x;
    for (int i = t; i < e; i += stride) atomicAdd(&g_cnt[dst[i]], 1);
}

// 3a) per-256-chunk sums
__global__ void scan_block_kernel(int n) {
    __shared__ int sh[256];
    int t = threadIdx.x;
    int i = blockIdx.x * 256 + t;
    sh[t] = (i < n) ? g_cnt[i] : 0;
    __syncthreads();
    for (int o = 128; o > 0; o >>= 1) {
        if (t < o) sh[t] += sh[t + o];
        __syncthreads();
    }
    if (t == 0) g_bsum[blockIdx.x] = sh[0];
}

// 3b) exclusive scan over the (<=512) block sums, one block
__global__ void scan_top_kernel(int nb) {
    __shared__ int sh[512];
    int t = threadIdx.x;
    int v = (t < nb) ? g_bsum[t] : 0;
    sh[t] = v;
    __syncthreads();
    for (int o = 1; o < 512; o <<= 1) {
        int add = (t >= o) ? sh[t - o] : 0;
        __syncthreads();
        sh[t] += add;
        __syncthreads();
    }
    if (t < nb) g_bsum[t] = sh[t] - v;   // exclusive
}

// 3c) finalize per-element exclusive offsets + scatter cursors
__global__ void scan_final_kernel(int n) {
    __shared__ int sh[256];
    int t = threadIdx.x;
    int i = blockIdx.x * 256 + t;
    int v = (i < n) ? g_cnt[i] : 0;
    sh[t] = v;
    __syncthreads();
    for (int o = 1; o < 256; o <<= 1) {
        int add = (t >= o) ? sh[t - o] : 0;
        __syncthreads();
        sh[t] += add;
        __syncthreads();
    }
    if (i < n) {
        int excl = sh[t] - v + g_bsum[blockIdx.x];
        g_off[i] = excl;
        g_woff[i] = excl;
    }
}

// ---------------------------------------------------------------------------
// 4) scatter edges into CSR order (src ids only; ex recomputed in agg)
// ---------------------------------------------------------------------------
__global__ void scatter_kernel(const int* __restrict__ src,
                               const int* __restrict__ dst, int e) {
    int t = blockIdx.x * blockDim.x + threadIdx.x;
    int stride = gridDim.x * blockDim.x;
    for (int i = t; i < e; i += stride) {
        int pos = atomicAdd(&g_woff[dst[i]], 1);
        g_srcs[pos] = src[i];
    }
}

// ---------------------------------------------------------------------------
// 5) fused aggregate + bias + |.| + LayerNorm + exact GELU  (warp per node)
//    SINGLE PASS: normalization is linear, so accumulate unnormalized
//    sum(ex*h) and the denominator sum(ex) together; divide at the end.
//    Every lane walks all edges (owns 4 cols), so each lane's sex is the
//    full per-head denominator — no reduction needed.
// ---------------------------------------------------------------------------
__global__ void agg_kernel(const float* __restrict__ bias,
                           const float* __restrict__ gamma,
                           const float* __restrict__ beta,
                           float* __restrict__ out, int n) {
    int lane = threadIdx.x & 31;
    int wid = (blockIdx.x * blockDim.x + threadIdx.x) >> 5;
    int nw = (gridDim.x * blockDim.x) >> 5;
    int head = lane >> 3;
    float4 bv = *(const float4*)&bias[lane * 4];
    float4 gv = *(const float4*)&gamma[lane * 4];
    float4 tv = *(const float4*)&beta[lane * 4];

    for (int d = wid; d < n; d += nw) {
        int base = g_off[d];
        int deg = g_cnt[d];
        float adh = g_adst[d * 4 + head];

        float4 acc = make_float4(0.f, 0.f, 0.f, 0.f);
        float sex = 0.f;                       // per-head denominator
        int j = 0;
        int deg8 = deg & ~7;
        for (; j < deg8; j += 8) {
            int e0 = base + j;
            int si[8];
            float vi[8];
            __half2 ph[8], qh[8];
#pragma unroll
            for (int u = 0; u < 8; u++) si[u] = g_srcs[e0 + u];
#pragma unroll
            for (int u = 0; u < 8; u++) {
                vi[u] = g_asrc[si[u] * 4 + head] + adh;
                ph[u] = *(const __half2*)&g_hh[si[u] * 128 + lane * 4];
                qh[u] = *(const __half2*)&g_hh[si[u] * 128 + lane * 4 + 2];
            }
#pragma unroll
            for (int u = 0; u < 8; u++) {
                float a0 = expf(vi[u] > 0.f ? vi[u] : 0.2f * vi[u]);
                sex += a0;
                float2 f;
                f = __half22float2(ph[u]); acc.x += f.x * a0; acc.y += f.y * a0;
                f = __half22float2(qh[u]); acc.z += f.x * a0; acc.w += f.y * a0;
            }
        }
        for (; j < deg; j++) {
            int s = g_srcs[base + j];
            float v0 = g_asrc[s * 4 + head] + adh;
            float a0 = expf(v0 > 0.f ? v0 : 0.2f * v0);
            sex += a0;
            __half2 p0 = *(const __half2*)&g_hh[s * 128 + lane * 4];
            __half2 q0 = *(const __half2*)&g_hh[s * 128 + lane * 4 + 2];
            float2 f;
            f = __half22float2(p0); acc.x += f.x * a0; acc.y += f.y * a0;
            f = __half22float2(q0); acc.z += f.x * a0; acc.w += f.y * a0;
        }
        float rinv = 1.0f / (sex + 1e-16f);

        // epilogue: normalize, bias, magnitude, LayerNorm, exact GELU
        float4 v;
        v.x = acc.x * rinv + bv.x; v.y = acc.y * rinv + bv.y;
        v.z = acc.z * rinv + bv.z; v.w = acc.w * rinv + bv.w;
        float4 m;
        m.x = sqrtf(v.x * v.x + 1e-12f);
        m.y = sqrtf(v.y * v.y + 1e-12f);
        m.z = sqrtf(v.z * v.z + 1e-12f);
        m.w = sqrtf(v.w * v.w + 1e-12f);
        float sum = m.x + m.y + m.z + m.w;
        float sq = m.x * m.x + m.y * m.y + m.z * m.z + m.w * m.w;
#pragma unroll
        for (int o = 16; o >= 1; o >>= 1) {
            sum += __shfl_xor_sync(0xFFFFFFFFu, sum, o);
            sq  += __shfl_xor_sync(0xFFFFFFFFu, sq, o);
        }
        float mu = sum * (1.0f / 128.0f);
        float var = sq * (1.0f / 128.0f) - mu * mu;
        float rstd = rsqrtf(var + 1e-5f);
        float4 r;
        float hx;
        hx = (m.x - mu) * rstd * gv.x + tv.x;
        r.x = 0.5f * hx * (1.0f + erff(hx * 0.70710678118654752f));
        hx = (m.y - mu) * rstd * gv.y + tv.y;
        r.y = 0.5f * hx * (1.0f + erff(hx * 0.70710678118654752f));
        hx = (m.z - mu) * rstd * gv.z + tv.z;
        r.z = 0.5f * hx * (1.0f + erff(hx * 0.70710678118654752f));
        hx = (m.w - mu) * rstd * gv.w + tv.w;
        r.w = 0.5f * hx * (1.0f + erff(hx * 0.70710678118654752f));
        *(float4*)&out[d * 128 + lane * 4] = r;
    }
}

// ---------------------------------------------------------------------------
// Launch: fork CSR build (edge-only deps) parallel to wsplit+gemm (x/W deps),
// join before agg.
// ---------------------------------------------------------------------------
extern "C" void kernel_launch(void* const* d_in, const int* in_sizes, int n_in,
                              void* d_out, int out_size) {
    const float* x       = (const float*)d_in[0];
    const int*   ei      = (const int*)d_in[1];   // int32 (JAX x64 disabled)
    const float* W       = (const float*)d_in[2];
    const float* att_src = (const float*)d_in[3];
    const float* att_dst = (const float*)d_in[4];
    const float* bias    = (const float*)d_in[5];
    // d_in[6] = phase (mathematically cancels)
    const float* gamma   = (const float*)d_in[7];
    const float* beta    = (const float*)d_in[8];
    float* out = (float*)d_out;

    int n = in_sizes[0] / 128;
    int e = in_sizes[1] / 2;
    const int* srcp = ei;
    const int* dstp = ei + e;
    int nb_scan = (n + 255) / 256;

    cudaStream_t s2;
    cudaEvent_t ev_fork, ev_join;
    cudaStreamCreateWithFlags(&s2, cudaStreamNonBlocking);
    cudaEventCreateWithFlags(&ev_fork, cudaEventDisableTiming);
    cudaEventCreateWithFlags(&ev_join, cudaEventDisableTiming);

    // fork: CSR chain on s2 (depends only on edge_index)
    cudaEventRecord(ev_fork, 0);
    cudaStreamWaitEvent(s2, ev_fork, 0);
    zero_cnt_kernel<<<296, 256, 0, s2>>>(n);
    hist_kernel<<<1184, 256, 0, s2>>>(dstp, e);
    scan_block_kernel<<<nb_scan, 256, 0, s2>>>(n);
    scan_top_kernel<<<1, 512, 0, s2>>>(nb_scan);
    scan_final_kernel<<<nb_scan, 256, 0, s2>>>(n);
    scatter_kernel<<<1184, 256, 0, s2>>>(srcp, dstp, e);
    cudaEventRecord(ev_join, s2);

    // main stream: GEMM chain (depends only on x, W, att)
    wsplit_kernel<<<64, 256>>>(W);
    gemm_tf32_kernel<<<(n + 63) / 64, 128, GEMM_SMEM>>>(x, att_src, att_dst, n);

    // join: agg needs both branches
    cudaStreamWaitEvent(0, ev_join, 0);
    agg_kernel<<<2368, 256>>>(bias, gamma, beta, out, n);
}

// round 17
// speedup vs baseline: 2.9102x; 1.0588x over previous
#include <cuda_runtime.h>
#include <cuda_fp16.h>
#include <math.h>

// Problem constants (fixed by the reference)
#define MAXN 100000
#define MAXE 1600000

// Scratch (device globals: allocation-free per harness rules).
__device__ __align__(16) __half g_hh[MAXN * 128]; // h in fp16 (gather path, 25.6 MB)
__device__ __align__(16) float g_asrc[MAXN * 4];  // a_src per node/head
__device__ __align__(16) float g_adst[MAXN * 4];  // a_dst per node/head
__device__ __align__(16) __half g_wh[128 * 128];  // fp16-hi of W, [col][k] (orig layout)
__device__ __align__(16) __half g_wl[128 * 128];  // fp16-lo of W, [col][k]
__device__ int g_srcs[MAXE];                      // src id per edge, CSR order
__device__ int g_cnt[MAXN];                       // in-degree
__device__ int g_off[MAXN];                       // CSR offsets (exclusive)
__device__ int g_woff[MAXN];                      // scatter cursors
__device__ int g_bsum[512];                       // block sums for scan

// m16n8k16 fp16 mma, fp32 accumulate
__device__ __forceinline__ void mma_f16(float* c, const unsigned* a,
                                        unsigned b0, unsigned b1) {
    asm volatile(
        "mma.sync.aligned.m16n8k16.row.col.f32.f16.f16.f32 "
        "{%0,%1,%2,%3}, {%4,%5,%6,%7}, {%8,%9}, {%0,%1,%2,%3};"
        : "+f"(c[0]), "+f"(c[1]), "+f"(c[2]), "+f"(c[3])
        : "r"(a[0]), "r"(a[1]), "r"(a[2]), "r"(a[3]), "r"(b0), "r"(b1));
}

// ---------------------------------------------------------------------------
// 0) zero degree counters
// ---------------------------------------------------------------------------
__global__ void zero_cnt_kernel(int n) {
    int t = blockIdx.x * blockDim.x + threadIdx.x;
    int stride = gridDim.x * blockDim.x;
    for (int i = t; i < n; i += stride) g_cnt[i] = 0;
}

// ---------------------------------------------------------------------------
// 0b) split W into fp16 hi/lo, keeping original [col][k] layout
// ---------------------------------------------------------------------------
__global__ void wsplit_kernel(const float* __restrict__ W) {
    int idx = blockIdx.x * blockDim.x + threadIdx.x;
    if (idx < 128 * 128) {
        float v = W[idx];
        __half hi = __float2half_rn(v);
        float lof = v - __half2float(hi);
        g_wh[idx] = hi;
        g_wl[idx] = __float2half_rn(lof);
    }
}

// ---------------------------------------------------------------------------
// 1) h = x @ W^T via 3-term fp16-split mma.m16n8k16 (fp32-accurate),
//    attn logits fused in epilogue.
//    Block: 64 rows x 128 cols, 4 warps; warp tile 64x32. h stored fp16.
//    x split hi/lo once at staging into smem half arrays.
// ---------------------------------------------------------------------------
#define PADH 136   // halves per smem row (17-word stride: conflict-free)
#define GEMM_SMEM (2 * 64 * PADH * 2)   // 34816 bytes (hi + lo half arrays)

__global__ void __launch_bounds__(128, 4)
gemm_f16_kernel(const float* __restrict__ x,
                const float* __restrict__ att_src,
                const float* __restrict__ att_dst, int n) {
    extern __shared__ __half sm16[];
    __half* xh = sm16;                 // [64][PADH] hi
    __half* xl = sm16 + 64 * PADH;     // [64][PADH] lo
    int tid = threadIdx.x;
    int row0 = blockIdx.x * 64;

    // stage x rows, splitting fp32 -> fp16 hi + lo (zero-fill tail)
    for (int idx = tid; idx < 64 * 32; idx += 128) {
        int r = idx >> 5, c4 = (idx & 31) * 4;
        int gr = row0 + r;
        float4 v = (gr < n) ? *(const float4*)&x[gr * 128 + c4]
                            : make_float4(0.f, 0.f, 0.f, 0.f);
        __half2 h0 = __floats2half2_rn(v.x, v.y);
        __half2 h1 = __floats2half2_rn(v.z, v.w);
        float2 b0 = __half22float2(h0);
        float2 b1 = __half22float2(h1);
        __half2 l0 = __floats2half2_rn(v.x - b0.x, v.y - b0.y);
        __half2 l1 = __floats2half2_rn(v.z - b1.x, v.w - b1.y);
        *(__half2*)&xh[r * PADH + c4]     = h0;
        *(__half2*)&xh[r * PADH + c4 + 2] = h1;
        *(__half2*)&xl[r * PADH + c4]     = l0;
        *(__half2*)&xl[r * PADH + c4 + 2] = l1;
    }
    __syncthreads();

    int w = tid >> 5;             // warp id = head id = col block
    int lane = tid & 31;
    int g = lane >> 2;            // 0..7
    int tig = lane & 3;           // 0..3
    int colbase = w * 32;

    float acc[4][4][4] = {};      // [m-tile][n-tile][frag]

    for (int k0 = 0; k0 < 128; k0 += 16) {
        unsigned ah[4][4], al[4][4];
#pragma unroll
        for (int mt = 0; mt < 4; mt++) {
            int r = mt * 16 + g;
            int kb = k0 + 2 * tig;
            // a-regs: [ (r,klow), (r+8,klow), (r,khigh), (r+8,khigh) ]
            ah[mt][0] = *(const unsigned*)&xh[r * PADH + kb];
            ah[mt][1] = *(const unsigned*)&xh[(r + 8) * PADH + kb];
            ah[mt][2] = *(const unsigned*)&xh[r * PADH + kb + 8];
            ah[mt][3] = *(const unsigned*)&xh[(r + 8) * PADH + kb + 8];
            al[mt][0] = *(const unsigned*)&xl[r * PADH + kb];
            al[mt][1] = *(const unsigned*)&xl[(r + 8) * PADH + kb];
            al[mt][2] = *(const unsigned*)&xl[r * PADH + kb + 8];
            al[mt][3] = *(const unsigned*)&xl[(r + 8) * PADH + kb + 8];
        }
#pragma unroll
        for (int nt = 0; nt < 4; nt++) {
            int c = colbase + nt * 8 + g;
            int kb = k0 + 2 * tig;
            unsigned bh0 = *(const unsigned*)&g_wh[c * 128 + kb];
            unsigned bh1 = *(const unsigned*)&g_wh[c * 128 + kb + 8];
            unsigned bl0 = *(const unsigned*)&g_wl[c * 128 + kb];
            unsigned bl1 = *(const unsigned*)&g_wl[c * 128 + kb + 8];
#pragma unroll
            for (int mt = 0; mt < 4; mt++) {
                mma_f16(acc[mt][nt], ah[mt], bh0, bh1);   // hi*hi
                mma_f16(acc[mt][nt], ah[mt], bl0, bl1);   // hi*lo
                mma_f16(acc[mt][nt], al[mt], bh0, bh1);   // lo*hi
            }
        }
    }

    // epilogue: store h (fp16) + fused attention logits for head w
    float as_c[4][2], ad_c[4][2];
#pragma unroll
    for (int nt = 0; nt < 4; nt++) {
        int col = colbase + nt * 8 + tig * 2;
        as_c[nt][0] = att_src[col]; as_c[nt][1] = att_src[col + 1];
        ad_c[nt][0] = att_dst[col]; ad_c[nt][1] = att_dst[col + 1];
    }
#pragma unroll
    for (int mt = 0; mt < 4; mt++) {
        int r0 = row0 + mt * 16 + g;
        int r1 = r0 + 8;
        float ps0 = 0.f, ps1 = 0.f, pd0 = 0.f, pd1 = 0.f;
#pragma unroll
        for (int nt = 0; nt < 4; nt++) {
            int cb = colbase + nt * 8 + tig * 2;
            if (r0 < n) *(__half2*)&g_hh[r0 * 128 + cb] =
                __float22half2_rn(make_float2(acc[mt][nt][0], acc[mt][nt][1]));
            if (r1 < n) *(__half2*)&g_hh[r1 * 128 + cb] =
                __float22half2_rn(make_float2(acc[mt][nt][2], acc[mt][nt][3]));
            ps0 += acc[mt][nt][0] * as_c[nt][0] + acc[mt][nt][1] * as_c[nt][1];
            ps1 += acc[mt][nt][2] * as_c[nt][0] + acc[mt][nt][3] * as_c[nt][1];
            pd0 += acc[mt][nt][0] * ad_c[nt][0] + acc[mt][nt][1] * ad_c[nt][1];
            pd1 += acc[mt][nt][2] * ad_c[nt][0] + acc[mt][nt][3] * ad_c[nt][1];
        }
        ps0 += __shfl_xor_sync(0xFFFFFFFFu, ps0, 1);
        ps0 += __shfl_xor_sync(0xFFFFFFFFu, ps0, 2);
        ps1 += __shfl_xor_sync(0xFFFFFFFFu, ps1, 1);
        ps1 += __shfl_xor_sync(0xFFFFFFFFu, ps1, 2);
        pd0 += __shfl_xor_sync(0xFFFFFFFFu, pd0, 1);
        pd0 += __shfl_xor_sync(0xFFFFFFFFu, pd0, 2);
        pd1 += __shfl_xor_sync(0xFFFFFFFFu, pd1, 1);
        pd1 += __shfl_xor_sync(0xFFFFFFFFu, pd1, 2);
        if (tig == 0) {
            if (r0 < n) { g_asrc[r0 * 4 + w] = ps0; g_adst[r0 * 4 + w] = pd0; }
            if (r1 < n) { g_asrc[r1 * 4 + w] = ps1; g_adst[r1 * 4 + w] = pd1; }
        }
    }
}

// ---------------------------------------------------------------------------
// 3) CSR build: histogram of dst degrees
// ---------------------------------------------------------------------------
__global__ void hist_kernel(const int* __restrict__ dst, int e) {
    int t = blockIdx.x * blockDim.x + threadIdx.x;
    int stride = gridDim.x * blockDim.x;
    for (int i = t; i < e; i += stride) atomicAdd(&g_cnt[dst[i]], 1);
}

// 3a) per-256-chunk sums
__global__ void scan_block_kernel(int n) {
    __shared__ int sh[256];
    int t = threadIdx.x;
    int i = blockIdx.x * 256 + t;
    sh[t] = (i < n) ? g_cnt[i] : 0;
    __syncthreads();
    for (int o = 128; o > 0; o >>= 1) {
        if (t < o) sh[t] += sh[t + o];
        __syncthreads();
    }
    if (t == 0) g_bsum[blockIdx.x] = sh[0];
}

// 3b) exclusive scan over the (<=512) block sums, one block
__global__ void scan_top_kernel(int nb) {
    __shared__ int sh[512];
    int t = threadIdx.x;
    int v = (t < nb) ? g_bsum[t] : 0;
    sh[t] = v;
    __syncthreads();
    for (int o = 1; o < 512; o <<= 1) {
        int add = (t >= o) ? sh[t - o] : 0;
        __syncthreads();
        sh[t] += add;
        __syncthreads();
    }
    if (t < nb) g_bsum[t] = sh[t] - v;   // exclusive
}

// 3c) finalize per-element exclusive offsets + scatter cursors
__global__ void scan_final_kernel(int n) {
    __shared__ int sh[256];
    int t = threadIdx.x;
    int i = blockIdx.x * 256 + t;
    int v = (i < n) ? g_cnt[i] : 0;
    sh[t] = v;
    __syncthreads();
    for (int o = 1; o < 256; o <<= 1) {
        int add = (t >= o) ? sh[t - o] : 0;
        __syncthreads();
        sh[t] += add;
        __syncthreads();
    }
    if (i < n) {
        int excl = sh[t] - v + g_bsum[blockIdx.x];
        g_off[i] = excl;
        g_woff[i] = excl;
    }
}

// ---------------------------------------------------------------------------
// 4) scatter edges into CSR order (src ids only; ex recomputed in agg)
// ---------------------------------------------------------------------------
__global__ void scatter_kernel(const int* __restrict__ src,
                               const int* __restrict__ dst, int e) {
    int t = blockIdx.x * blockDim.x + threadIdx.x;
    int stride = gridDim.x * blockDim.x;
    for (int i = t; i < e; i += stride) {
        int pos = atomicAdd(&g_woff[dst[i]], 1);
        g_srcs[pos] = src[i];
    }
}

// ---------------------------------------------------------------------------
// 5) fused aggregate + bias + |.| + LayerNorm + exact GELU  (warp per node)
//    Single pass: unnormalized sum + denominator together, divide at end.
// ---------------------------------------------------------------------------
__global__ void agg_kernel(const float* __restrict__ bias,
                           const float* __restrict__ gamma,
                           const float* __restrict__ beta,
                           float* __restrict__ out, int n) {
    int lane = threadIdx.x & 31;
    int wid = (blockIdx.x * blockDim.x + threadIdx.x) >> 5;
    int nw = (gridDim.x * blockDim.x) >> 5;
    int head = lane >> 3;
    float4 bv = *(const float4*)&bias[lane * 4];
    float4 gv = *(const float4*)&gamma[lane * 4];
    float4 tv = *(const float4*)&beta[lane * 4];

    for (int d = wid; d < n; d += nw) {
        int base = g_off[d];
        int deg = g_cnt[d];
        float adh = g_adst[d * 4 + head];

        float4 acc = make_float4(0.f, 0.f, 0.f, 0.f);
        float sex = 0.f;                       // per-head denominator
        int j = 0;
        int deg8 = deg & ~7;
        for (; j < deg8; j += 8) {
            int e0 = base + j;
            int si[8];
            float vi[8];
            __half2 ph[8], qh[8];
#pragma unroll
            for (int u = 0; u < 8; u++) si[u] = g_srcs[e0 + u];
#pragma unroll
            for (int u = 0; u < 8; u++) {
                vi[u] = g_asrc[si[u] * 4 + head] + adh;
                ph[u] = *(const __half2*)&g_hh[si[u] * 128 + lane * 4];
                qh[u] = *(const __half2*)&g_hh[si[u] * 128 + lane * 4 + 2];
            }
#pragma unroll
            for (int u = 0; u < 8; u++) {
                float a0 = expf(vi[u] > 0.f ? vi[u] : 0.2f * vi[u]);
                sex += a0;
                float2 f;
                f = __half22float2(ph[u]); acc.x += f.x * a0; acc.y += f.y * a0;
                f = __half22float2(qh[u]); acc.z += f.x * a0; acc.w += f.y * a0;
            }
        }
        for (; j < deg; j++) {
            int s = g_srcs[base + j];
            float v0 = g_asrc[s * 4 + head] + adh;
            float a0 = expf(v0 > 0.f ? v0 : 0.2f * v0);
            sex += a0;
            __half2 p0 = *(const __half2*)&g_hh[s * 128 + lane * 4];
            __half2 q0 = *(const __half2*)&g_hh[s * 128 + lane * 4 + 2];
            float2 f;
            f = __half22float2(p0); acc.x += f.x * a0; acc.y += f.y * a0;
            f = __half22float2(q0); acc.z += f.x * a0; acc.w += f.y * a0;
        }
        float rinv = 1.0f / (sex + 1e-16f);

        // epilogue: normalize, bias, magnitude, LayerNorm, exact GELU
        float4 v;
        v.x = acc.x * rinv + bv.x; v.y = acc.y * rinv + bv.y;
        v.z = acc.z * rinv + bv.z; v.w = acc.w * rinv + bv.w;
        float4 m;
        m.x = sqrtf(v.x * v.x + 1e-12f);
        m.y = sqrtf(v.y * v.y + 1e-12f);
        m.z = sqrtf(v.z * v.z + 1e-12f);
        m.w = sqrtf(v.w * v.w + 1e-12f);
        float sum = m.x + m.y + m.z + m.w;
        float sq = m.x * m.x + m.y * m.y + m.z * m.z + m.w * m.w;
#pragma unroll
        for (int o = 16; o >= 1; o >>= 1) {
            sum += __shfl_xor_sync(0xFFFFFFFFu, sum, o);
            sq  += __shfl_xor_sync(0xFFFFFFFFu, sq, o);
        }
        float mu = sum * (1.0f / 128.0f);
        float var = sq * (1.0f / 128.0f) - mu * mu;
        float rstd = rsqrtf(var + 1e-5f);
        float4 r;
        float hx;
        hx = (m.x - mu) * rstd * gv.x + tv.x;
        r.x = 0.5f * hx * (1.0f + erff(hx * 0.70710678118654752f));
        hx = (m.y - mu) * rstd * gv.y + tv.y;
        r.y = 0.5f * hx * (1.0f + erff(hx * 0.70710678118654752f));
        hx = (m.z - mu) * rstd * gv.z + tv.z;
        r.z = 0.5f * hx * (1.0f + erff(hx * 0.70710678118654752f));
        hx = (m.w - mu) * rstd * gv.w + tv.w;
        r.w = 0.5f * hx * (1.0f + erff(hx * 0.70710678118654752f));
        *(float4*)&out[d * 128 + lane * 4] = r;
    }
}

// ---------------------------------------------------------------------------
// Launch: fork CSR build (edge-only deps) parallel to wsplit+gemm (x/W deps),
// join before agg.
// ---------------------------------------------------------------------------
extern "C" void kernel_launch(void* const* d_in, const int* in_sizes, int n_in,
                              void* d_out, int out_size) {
    const float* x       = (const float*)d_in[0];
    const int*   ei      = (const int*)d_in[1];   // int32 (JAX x64 disabled)
    const float* W       = (const float*)d_in[2];
    const float* att_src = (const float*)d_in[3];
    const float* att_dst = (const float*)d_in[4];
    const float* bias    = (const float*)d_in[5];
    // d_in[6] = phase (mathematically cancels)
    const float* gamma   = (const float*)d_in[7];
    const float* beta    = (const float*)d_in[8];
    float* out = (float*)d_out;

    int n = in_sizes[0] / 128;
    int e = in_sizes[1] / 2;
    const int* srcp = ei;
    const int* dstp = ei + e;
    int nb_scan = (n + 255) / 256;

    cudaStream_t s2;
    cudaEvent_t ev_fork, ev_join;
    cudaStreamCreateWithFlags(&s2, cudaStreamNonBlocking);
    cudaEventCreateWithFlags(&ev_fork, cudaEventDisableTiming);
    cudaEventCreateWithFlags(&ev_join, cudaEventDisableTiming);

    // fork: CSR chain on s2 (depends only on edge_index)
    cudaEventRecord(ev_fork, 0);
    cudaStreamWaitEvent(s2, ev_fork, 0);
    zero_cnt_kernel<<<296, 256, 0, s2>>>(n);
    hist_kernel<<<1184, 256, 0, s2>>>(dstp, e);
    scan_block_kernel<<<nb_scan, 256, 0, s2>>>(n);
    scan_top_kernel<<<1, 512, 0, s2>>>(nb_scan);
    scan_final_kernel<<<nb_scan, 256, 0, s2>>>(n);
    scatter_kernel<<<1184, 256, 0, s2>>>(srcp, dstp, e);
    cudaEventRecord(ev_join, s2);

    // main stream: GEMM chain (depends only on x, W, att)
    wsplit_kernel<<<64, 256>>>(W);
    gemm_f16_kernel<<<(n + 63) / 64, 128, GEMM_SMEM>>>(x, att_src, att_dst, n);

    // join: agg needs both branches
    cudaStreamWaitEvent(0, ev_join, 0);
    agg_kernel<<<2368, 256>>>(bias, gamma, beta, out, n);
}